// round 8
// baseline (speedup 1.0000x reference)
#include <cuda_runtime.h>
#include <cuda_bf16.h>
#include <math.h>
#include <stdint.h>

#define S_LEN 2048
#define HID   2048
#define NH    32
#define NKV   8
#define HD    64

// ---------------------------------------------------------------------------
// Scratch (device globals)
// ---------------------------------------------------------------------------
__device__ float g_q[NH * S_LEN * HD];     // pre-RoPE Q fp32
__device__ float g_k[NKV * S_LEN * HD];    // pre-RoPE K fp32

__device__ __nv_bfloat16 g_Xh[S_LEN * HID],  g_Xl[S_LEN * HID];
__device__ __nv_bfloat16 g_Wqh[HID * HID],   g_Wql[HID * HID];
__device__ __nv_bfloat16 g_Wkh[NKV*HD*HID],  g_Wkl[NKV*HD*HID];
__device__ __nv_bfloat16 g_Wvh[NKV*HD*HID],  g_Wvl[NKV*HD*HID];
__device__ __nv_bfloat16 g_Woh[HID * HID],   g_Wol[HID * HID];
__device__ __nv_bfloat16 g_Ch[S_LEN * HID],  g_Cl[S_LEN * HID];    // attn out split

__device__ __nv_bfloat16 g_qh[NH * S_LEN * HD],  g_ql[NH * S_LEN * HD];   // post-RoPE
__device__ __nv_bfloat16 g_kh[NKV * S_LEN * HD], g_kl[NKV * S_LEN * HD];
__device__ __nv_bfloat16 g_vh[NKV * S_LEN * HD], g_vl[NKV * S_LEN * HD];

// ---------------------------------------------------------------------------
// PTX helpers (plain sm_80+ features only)
// ---------------------------------------------------------------------------
__device__ __forceinline__ uint32_t s2u(const void* p) {
    uint32_t a;
    asm("{ .reg .u64 t; cvta.to.shared.u64 t, %1; cvt.u32.u64 %0, t; }" : "=r"(a) : "l"(p));
    return a;
}

__device__ __forceinline__ void ldsm4(uint32_t* r, uint32_t addr) {
    asm volatile("ldmatrix.sync.aligned.m8n8.x4.shared.b16 {%0,%1,%2,%3}, [%4];"
                 : "=r"(r[0]), "=r"(r[1]), "=r"(r[2]), "=r"(r[3]) : "r"(addr));
}

__device__ __forceinline__ void ldsm4t(uint32_t* r, uint32_t addr) {
    asm volatile("ldmatrix.sync.aligned.m8n8.x4.trans.shared.b16 {%0,%1,%2,%3}, [%4];"
                 : "=r"(r[0]), "=r"(r[1]), "=r"(r[2]), "=r"(r[3]) : "r"(addr));
}

__device__ __forceinline__ void mma16816(float* d, uint32_t a0, uint32_t a1, uint32_t a2,
                                         uint32_t a3, uint32_t b0, uint32_t b1) {
    asm volatile(
        "mma.sync.aligned.m16n8k16.row.col.f32.bf16.bf16.f32 "
        "{%0,%1,%2,%3}, {%4,%5,%6,%7}, {%8,%9}, {%0,%1,%2,%3};"
        : "+f"(d[0]), "+f"(d[1]), "+f"(d[2]), "+f"(d[3])
        : "r"(a0), "r"(a1), "r"(a2), "r"(a3), "r"(b0), "r"(b1));
}

__device__ __forceinline__ void cpa16(uint32_t saddr, const void* g) {
    asm volatile("cp.async.cg.shared.global [%0], [%1], 16;" :: "r"(saddr), "l"(g) : "memory");
}

__device__ __forceinline__ uint32_t packbf(float lo, float hi) {
    uint32_t r;
    asm("cvt.rn.bf16x2.f32 %0, %1, %2;" : "=r"(r) : "f"(hi), "f"(lo));
    return r;
}
__device__ __forceinline__ float lo_of(uint32_t p) { return __uint_as_float(p << 16); }
__device__ __forceinline__ float hi_of(uint32_t p) { return __uint_as_float(p & 0xFFFF0000u); }

// ---------------------------------------------------------------------------
// Merged fp32 -> (bf16 hi, bf16 lo) split for all 5 inputs. One launch.
// ---------------------------------------------------------------------------
#define N_X4  1048576
#define N_WQ4 1048576
#define N_WK4 262144
#define N_WV4 262144
#define N_WO4 1048576
#define N_ALL4 (N_X4 + N_WQ4 + N_WK4 + N_WV4 + N_WO4)

__global__ __launch_bounds__(256) void split_all(const float* __restrict__ X,
                                                 const float* __restrict__ Wq,
                                                 const float* __restrict__ Wk,
                                                 const float* __restrict__ Wv,
                                                 const float* __restrict__ Wo)
{
    const int i = blockIdx.x * 256 + threadIdx.x;
    const float* src;
    __nv_bfloat16 *hi, *lo;
    int off;
    if (i < N_X4)                       { src = X;  hi = g_Xh;  lo = g_Xl;  off = i; }
    else if (i < N_X4 + N_WQ4)          { src = Wq; hi = g_Wqh; lo = g_Wql; off = i - N_X4; }
    else if (i < N_X4 + N_WQ4 + N_WK4)  { src = Wk; hi = g_Wkh; lo = g_Wkl; off = i - N_X4 - N_WQ4; }
    else if (i < N_X4 + N_WQ4 + N_WK4 + N_WV4)
                                        { src = Wv; hi = g_Wvh; lo = g_Wvl; off = i - N_X4 - N_WQ4 - N_WK4; }
    else                                { src = Wo; hi = g_Woh; lo = g_Wol; off = i - N_X4 - N_WQ4 - N_WK4 - N_WV4; }

    float4 v = ((const float4*)src)[off];
    __nv_bfloat16 h[4], l[4];
    float f[4] = {v.x, v.y, v.z, v.w};
#pragma unroll
    for (int k = 0; k < 4; ++k) {
        h[k] = __float2bfloat16(f[k]);
        l[k] = __float2bfloat16(f[k] - __bfloat162float(h[k]));
    }
    *(uint64_t*)(hi + 4 * off) = *(uint64_t*)h;
    *(uint64_t*)(lo + 4 * off) = *(uint64_t*)l;
}

// ---------------------------------------------------------------------------
// 256x128 split-bf16 HMMA GEMM, 2-stage cp.async, combined [hi|lo] smem rows.
// MODE 0: fused QKV — N-space [Wq(2048) | Wk(512) | Wv(512)], grid (24, 8)
// MODE 1: O projection, grid (16, 8)
// smem row: [hi(32 halfs) | lo(32 halfs)] pad to 72 halfs (144B, conflict-free).
//   A region: 256 rows x 72 halfs = 36864 B ; B region: 128 x 72 = 18432 B
//   stage = 55296 B ; 2 stages = 110592 B dynamic.
// ---------------------------------------------------------------------------
#define GA_B 36864
#define GSTAGE_B 55296
#define GEMM_SMEM (2 * GSTAGE_B)

template <int MODE>
__global__ __launch_bounds__(256) void hgemm3_k(const float* __restrict__ bq,
                                                const float* __restrict__ bk,
                                                const float* __restrict__ bv,
                                                float* __restrict__ outp)
{
    extern __shared__ __nv_bfloat16 sm[];
    const int t = threadIdx.x, w = t >> 5, lane = t & 31;
    const int bm = blockIdx.y * 256;
    const int bn = blockIdx.x * 128;
    const int wm = (w >> 1) * 64;     // 0,64,128,192
    const int wn = (w & 1) * 64;      // 0,64

    const __nv_bfloat16 *Ah, *Al, *Bh, *Bl;
    const float* bias = nullptr;
    int outsel, bcol0;
    if (MODE == 0) {
        Ah = g_Xh; Al = g_Xl;
        if (bn < 2048)      { Bh = g_Wqh; Bl = g_Wql; bias = bq; outsel = 0; bcol0 = bn; }
        else if (bn < 2560) { Bh = g_Wkh; Bl = g_Wkl; bias = bk; outsel = 1; bcol0 = bn - 2048; }
        else                { Bh = g_Wvh; Bl = g_Wvl; bias = bv; outsel = 2; bcol0 = bn - 2560; }
    } else {
        Ah = g_Ch; Al = g_Cl; Bh = g_Woh; Bl = g_Wol; outsel = 3; bcol0 = bn;
    }

    const __nv_bfloat16* pAh = Ah + (size_t)bm * HID;
    const __nv_bfloat16* pAl = Al + (size_t)bm * HID;
    const __nv_bfloat16* pBh = Bh + (size_t)bcol0 * HID;
    const __nv_bfloat16* pBl = Bl + (size_t)bcol0 * HID;

    const uint32_t sb = s2u(sm);
    const uint32_t a_r = lane & 15, a_c8 = (lane >> 4) << 3;
    const uint32_t b_r = ((lane >> 4) << 3) + (lane & 7), b_c8 = ((lane >> 3) & 1) << 3;

    float acc[4][8][4];
#pragma unroll
    for (int mi = 0; mi < 4; ++mi)
#pragma unroll
        for (int ni = 0; ni < 8; ++ni)
#pragma unroll
            for (int r = 0; r < 4; ++r) acc[mi][ni][r] = 0.0f;

#define ISSUE(ktv, stg)                                                              \
    {                                                                                \
        const int _kt = (ktv);                                                       \
        const uint32_t _s = sb + (uint32_t)(stg) * GSTAGE_B;                         \
        _Pragma("unroll")                                                            \
        for (int i = 0; i < 8; ++i) {                                                \
            const int idx = i * 256 + t;                                             \
            const int row = idx >> 3, sub = idx & 7;                                 \
            const __nv_bfloat16* src = (sub < 4 ? pAh : pAl)                         \
                                       + (size_t)row * HID + _kt + (sub & 3) * 8;    \
            cpa16(_s + (uint32_t)(row * 72 + sub * 8) * 2, src);                     \
        }                                                                            \
        _Pragma("unroll")                                                            \
        for (int i = 0; i < 4; ++i) {                                                \
            const int idx = i * 256 + t;                                             \
            const int row = idx >> 3, sub = idx & 7;                                 \
            const __nv_bfloat16* src = (sub < 4 ? pBh : pBl)                         \
                                       + (size_t)row * HID + _kt + (sub & 3) * 8;    \
            cpa16(_s + GA_B + (uint32_t)(row * 72 + sub * 8) * 2, src);              \
        }                                                                            \
        asm volatile("cp.async.commit_group;" ::: "memory");                         \
    }

    ISSUE(0, 0);

    for (int it = 0; it < HID / 32; ++it) {
        const int cur = it & 1;
        if (it < HID / 32 - 1) {
            ISSUE((it + 1) * 32, cur ^ 1);
            asm volatile("cp.async.wait_group 1;" ::: "memory");
        } else {
            asm volatile("cp.async.wait_group 0;" ::: "memory");
        }
        __syncthreads();

        const uint32_t st = sb + (uint32_t)cur * GSTAGE_B;
#pragma unroll
        for (int ks = 0; ks < 2; ++ks) {
            const uint32_t k0 = ks * 16;
            // B fragments (reused across all mi)
            uint32_t bh[4][4], bl[4][4];
#pragma unroll
            for (int pi = 0; pi < 4; ++pi) {
                const uint32_t roff = st + GA_B + ((wn + pi * 16 + b_r) * 72) * 2;
                ldsm4(bh[pi], roff + (k0 + b_c8) * 2);
                ldsm4(bl[pi], roff + (32 + k0 + b_c8) * 2);
            }
#pragma unroll
            for (int mi = 0; mi < 4; ++mi) {
                uint32_t ah[4], al[4];
                const uint32_t roff = st + ((wm + mi * 16 + a_r) * 72) * 2;
                ldsm4(ah, roff + (k0 + a_c8) * 2);
                ldsm4(al, roff + (32 + k0 + a_c8) * 2);
#pragma unroll
                for (int pi = 0; pi < 4; ++pi) {
#pragma unroll
                    for (int half = 0; half < 2; ++half) {
                        const int ni = pi * 2 + half;
                        const uint32_t B0 = bh[pi][half * 2], B1 = bh[pi][half * 2 + 1];
                        const uint32_t C0 = bl[pi][half * 2], C1 = bl[pi][half * 2 + 1];
                        mma16816(acc[mi][ni], ah[0], ah[1], ah[2], ah[3], B0, B1);
                        mma16816(acc[mi][ni], ah[0], ah[1], ah[2], ah[3], C0, C1);
                        mma16816(acc[mi][ni], al[0], al[1], al[2], al[3], B0, B1);
                    }
                }
            }
        }
        __syncthreads();
    }
#undef ISSUE

    // Epilogue
#pragma unroll
    for (int mi = 0; mi < 4; ++mi) {
#pragma unroll
        for (int ni = 0; ni < 8; ++ni) {
            const int lcol = wn + ni * 8 + 2 * (lane & 3);
            const int col = bcol0 + lcol;
            float b0 = 0.f, b1 = 0.f;
            if (MODE == 0) { b0 = bias[col]; b1 = bias[col + 1]; }
#pragma unroll
            for (int rr = 0; rr < 2; ++rr) {
                const int row = bm + wm + mi * 16 + (lane >> 2) + rr * 8;
                float vx = acc[mi][ni][rr * 2 + 0] + b0;
                float vy = acc[mi][ni][rr * 2 + 1] + b1;
                if (outsel == 0 || outsel == 1) {
                    const int head = col >> 6, d = col & 63;
                    float* dst = (outsel == 0) ? g_q : g_k;
                    float2 v2 = {vx, vy};
                    *(float2*)(dst + ((size_t)head * S_LEN + row) * HD + d) = v2;
                } else if (outsel == 2) {
                    const int head = col >> 6, d = col & 63;
                    uint32_t ph = packbf(vx, vy);
                    uint32_t pl = packbf(vx - lo_of(ph), vy - hi_of(ph));
                    const size_t off = ((size_t)head * S_LEN + row) * HD + d;
                    *(uint32_t*)(g_vh + off) = ph;
                    *(uint32_t*)(g_vl + off) = pl;
                } else {
                    float2 v2 = {vx, vy};
                    *(float2*)(outp + (size_t)row * HID + col) = v2;
                }
            }
        }
    }
}

// ---------------------------------------------------------------------------
// RoPE for Q and K in one launch.
// ---------------------------------------------------------------------------
#define ROPE_Q_N (NH * S_LEN * 16)
#define ROPE_K_N (NKV * S_LEN * 16)

__global__ __launch_bounds__(256) void rope_all()
{
    int idx = blockIdx.x * 256 + threadIdx.x;
    const float* srcb;
    __nv_bfloat16 *dhb, *dlb;
    if (idx < ROPE_Q_N) { srcb = g_q; dhb = g_qh; dlb = g_ql; }
    else                { srcb = g_k; dhb = g_kh; dlb = g_kl; idx -= ROPE_Q_N; }

    const int j2 = (idx & 15) * 2;
    const int s = (idx >> 4) & (S_LEN - 1);
    const int h = idx >> 15;
    const size_t base = ((size_t)h * S_LEN + s) * HD;

    const float* src = srcb + base;
    float y1[2], y2[2];
#pragma unroll
    for (int e = 0; e < 2; ++e) {
        const int j = j2 + e;
        const float inv_freq = powf(10000.0f, -((float)(2 * j)) / 64.0f);
        float sn, cs;
        sincosf((float)s * inv_freq, &sn, &cs);
        const float x1 = src[j], x2 = src[j + 32];
        y1[e] = x1 * cs - x2 * sn;
        y2[e] = x2 * cs + x1 * sn;
    }
    __nv_bfloat16* dh = dhb + base;
    __nv_bfloat16* dl = dlb + base;
    uint32_t p1 = packbf(y1[0], y1[1]);
    uint32_t p2 = packbf(y2[0], y2[1]);
    *(uint32_t*)(dh + j2) = p1;
    *(uint32_t*)(dh + j2 + 32) = p2;
    *(uint32_t*)(dl + j2) = packbf(y1[0] - lo_of(p1), y1[1] - hi_of(p1));
    *(uint32_t*)(dl + j2 + 32) = packbf(y2[0] - lo_of(p2), y2[1] - hi_of(p2));
}

// ---------------------------------------------------------------------------
// HMMA flash attention, split pipeline (round-7 proven: 197us).
// ---------------------------------------------------------------------------
#define TILE_B 9216
#define AT_Q   0
#define AT_K0  (2 * TILE_B)
#define AT_K1  (4 * TILE_B)
#define AT_V   (6 * TILE_B)
#define ATTN_SMEM (8 * TILE_B)     // 73728

__global__ __launch_bounds__(128, 3) void attn_k()
{
    extern __shared__ __nv_bfloat16 smb[];
    const uint32_t sb = s2u(smb);
    const int h = blockIdx.y;
    const int zz = blockIdx.x;
    const int qb = (zz & 1) ? (31 - (zz >> 1)) : (zz >> 1);
    const int kvh = h >> 2;

    const int t = threadIdx.x, w = t >> 5, lane = t & 31;
    const size_t kvbase = (size_t)kvh * S_LEN * HD;

#define CPKV(dstoff, srch, srcl)                                                    \
    {                                                                               \
        _Pragma("unroll")                                                           \
        for (int ii = 0; ii < 8; ++ii) {                                            \
            const int tile = ii >> 2;                                               \
            const int rem = (ii & 3) * 128 + t;                                     \
            const int row = rem >> 3, ch = rem & 7;                                 \
            cpa16(sb + (dstoff) + tile * TILE_B + (row * 72 + ch * 8) * 2,          \
                  (tile ? (srcl) : (srch)) + row * 64 + ch * 8);                    \
        }                                                                           \
        asm volatile("cp.async.commit_group;" ::: "memory");                        \
    }

    CPKV(AT_K0, g_kh + kvbase, g_kl + kvbase);

    {
        const __nv_bfloat16* qh = g_qh + ((size_t)h * S_LEN + (size_t)qb * 64) * HD;
        const __nv_bfloat16* ql = g_ql + ((size_t)h * S_LEN + (size_t)qb * 64) * HD;
#pragma unroll
        for (int ii = 0; ii < 4; ++ii) {
            const int i = ii * 128 + t;
            const int row = i >> 3, ch = i & 7;
            *(uint4*)((char*)smb + AT_Q + (row * 72 + ch * 8) * 2) =
                *(const uint4*)(qh + row * 64 + ch * 8);
            *(uint4*)((char*)smb + AT_Q + TILE_B + (row * 72 + ch * 8) * 2) =
                *(const uint4*)(ql + row * 64 + ch * 8);
        }
    }
    __syncthreads();

    const uint32_t a_r = lane & 15, a_c8 = (lane >> 4) << 3;
    const uint32_t b_r = ((lane >> 4) << 3) + (lane & 7), b_c8 = ((lane >> 3) & 1) << 3;
    uint32_t qfh[4][4], qfl[4][4];
#pragma unroll
    for (int ks = 0; ks < 4; ++ks) {
        uint32_t off = ((w * 16 + a_r) * 72 + ks * 16 + a_c8) * 2;
        ldsm4(qfh[ks], sb + AT_Q + off);
        ldsm4(qfl[ks], sb + AT_Q + TILE_B + off);
    }

    float oacc[8][4];
#pragma unroll
    for (int nt = 0; nt < 8; ++nt)
#pragma unroll
        for (int e = 0; e < 4; ++e) oacc[nt][e] = 0.0f;
    float m_i[2] = {-1e30f, -1e30f}, l_i[2] = {0.0f, 0.0f};

    const int grow0 = qb * 64 + w * 16 + (lane >> 2);

    for (int kb = 0; kb <= qb; ++kb) {
        const uint32_t KHB = (kb & 1) ? AT_K1 : AT_K0;
        const uint32_t KLB = KHB + TILE_B;
        __syncthreads();
        {
            const size_t vb = kvbase + (size_t)kb * 64 * HD;
            CPKV(AT_V, g_vh + vb, g_vl + vb);
        }
        asm volatile("cp.async.wait_group 1;" ::: "memory");
        __syncthreads();

        float sacc[8][4];
#pragma unroll
        for (int nt = 0; nt < 8; ++nt)
#pragma unroll
            for (int e = 0; e < 4; ++e) sacc[nt][e] = 0.0f;

#pragma unroll
        for (int ks = 0; ks < 4; ++ks) {
#pragma unroll
            for (int np = 0; np < 4; ++np) {
                uint32_t BH[4], BL[4];
                uint32_t off = ((np * 16 + b_r) * 72 + ks * 16 + b_c8) * 2;
                ldsm4(BH, sb + KHB + off);
                ldsm4(BL, sb + KLB + off);
#pragma unroll
                for (int half = 0; half < 2; ++half) {
                    const int nt = np * 2 + half;
                    mma16816(sacc[nt], qfh[ks][0], qfh[ks][1], qfh[ks][2], qfh[ks][3],
                             BH[half * 2], BH[half * 2 + 1]);
                    mma16816(sacc[nt], qfh[ks][0], qfh[ks][1], qfh[ks][2], qfh[ks][3],
                             BL[half * 2], BL[half * 2 + 1]);
                    mma16816(sacc[nt], qfl[ks][0], qfl[ks][1], qfl[ks][2], qfl[ks][3],
                             BH[half * 2], BH[half * 2 + 1]);
                }
            }
        }

        if (kb < qb) {
            const size_t nb = kvbase + (size_t)(kb + 1) * 64 * HD;
            const uint32_t nstage = (kb & 1) ? AT_K0 : AT_K1;
            CPKV(nstage, g_kh + nb, g_kl + nb);
        }

        const bool diag = (kb == qb);
        float mt[2] = {-1e30f, -1e30f};
#pragma unroll
        for (int nt = 0; nt < 8; ++nt) {
#pragma unroll
            for (int e = 0; e < 4; ++e) {
                float v = sacc[nt][e] * 0.125f;
                v = fminf(fmaxf(v, -50.0f), 50.0f);
                if (diag) {
                    const int col = kb * 64 + nt * 8 + 2 * (lane & 3) + (e & 1);
                    const int row = grow0 + (e >> 1) * 8;
                    if (col > row) v = -1e30f;
                }
                sacc[nt][e] = v;
                mt[e >> 1] = fmaxf(mt[e >> 1], v);
            }
        }
#pragma unroll
        for (int o = 1; o < 4; o <<= 1) {
            mt[0] = fmaxf(mt[0], __shfl_xor_sync(0xffffffffu, mt[0], o));
            mt[1] = fmaxf(mt[1], __shfl_xor_sync(0xffffffffu, mt[1], o));
        }
        float corr[2], rs[2] = {0.0f, 0.0f};
#pragma unroll
        for (int rr = 0; rr < 2; ++rr) {
            const float mn = fmaxf(m_i[rr], mt[rr]);
            corr[rr] = __expf(m_i[rr] - mn);
            m_i[rr] = mn;
        }
#pragma unroll
        for (int nt = 0; nt < 8; ++nt)
#pragma unroll
            for (int e = 0; e < 4; ++e) {
                const float p = __expf(sacc[nt][e] - m_i[e >> 1]);
                sacc[nt][e] = p;
                rs[e >> 1] += p;
            }
#pragma unroll
        for (int o = 1; o < 4; o <<= 1) {
            rs[0] += __shfl_xor_sync(0xffffffffu, rs[0], o);
            rs[1] += __shfl_xor_sync(0xffffffffu, rs[1], o);
        }
#pragma unroll
        for (int rr = 0; rr < 2; ++rr) l_i[rr] = l_i[rr] * corr[rr] + rs[rr];
#pragma unroll
        for (int nt = 0; nt < 8; ++nt)
#pragma unroll
            for (int e = 0; e < 4; ++e) oacc[nt][e] *= corr[e >> 1];

        if (kb < qb) asm volatile("cp.async.wait_group 1;" ::: "memory");
        else         asm volatile("cp.async.wait_group 0;" ::: "memory");
        __syncthreads();

#pragma unroll
        for (int ks = 0; ks < 4; ++ks) {
            const int L = 2 * ks, R = 2 * ks + 1;
            uint32_t ph[4], pl[4];
            ph[0] = packbf(sacc[L][0], sacc[L][1]);
            ph[1] = packbf(sacc[L][2], sacc[L][3]);
            ph[2] = packbf(sacc[R][0], sacc[R][1]);
            ph[3] = packbf(sacc[R][2], sacc[R][3]);
            pl[0] = packbf(sacc[L][0] - lo_of(ph[0]), sacc[L][1] - hi_of(ph[0]));
            pl[1] = packbf(sacc[L][2] - lo_of(ph[1]), sacc[L][3] - hi_of(ph[1]));
            pl[2] = packbf(sacc[R][0] - lo_of(ph[2]), sacc[R][1] - hi_of(ph[2]));
            pl[3] = packbf(sacc[R][2] - lo_of(ph[3]), sacc[R][3] - hi_of(ph[3]));
#pragma unroll
            for (int dp = 0; dp < 4; ++dp) {
                uint32_t VH4[4], VL4[4];
                uint32_t voff = ((ks * 16 + (lane & 7) + ((lane >> 3) & 1) * 8) * 72
                                 + dp * 16 + ((lane >> 4) << 3)) * 2;
                ldsm4t(VH4, sb + AT_V + voff);
                ldsm4t(VL4, sb + AT_V + TILE_B + voff);
#pragma unroll
                for (int half = 0; half < 2; ++half) {
                    const int nt = dp * 2 + half;
                    mma16816(oacc[nt], ph[0], ph[1], ph[2], ph[3],
                             VH4[half * 2], VH4[half * 2 + 1]);
                    mma16816(oacc[nt], ph[0], ph[1], ph[2], ph[3],
                             VL4[half * 2], VL4[half * 2 + 1]);
                    mma16816(oacc[nt], pl[0], pl[1], pl[2], pl[3],
                             VH4[half * 2], VH4[half * 2 + 1]);
                }
            }
        }
    }
#undef CPKV

    const float inv0 = 1.0f / l_i[0], inv1 = 1.0f / l_i[1];
#pragma unroll
    for (int nt = 0; nt < 8; ++nt) {
#pragma unroll
        for (int rr = 0; rr < 2; ++rr) {
            const float inv = rr ? inv1 : inv0;
            const float v0 = oacc[nt][rr * 2 + 0] * inv;
            const float v1 = oacc[nt][rr * 2 + 1] * inv;
            const int srow = qb * 64 + w * 16 + (lane >> 2) + rr * 8;
            const int col = h * 64 + nt * 8 + 2 * (lane & 3);
            uint32_t ph = packbf(v0, v1);
            uint32_t pl = packbf(v0 - lo_of(ph), v1 - hi_of(ph));
            *(uint32_t*)(g_Ch + (size_t)srow * HID + col) = ph;
            *(uint32_t*)(g_Cl + (size_t)srow * HID + col) = pl;
        }
    }
}

// ---------------------------------------------------------------------------
// Launcher
// ---------------------------------------------------------------------------
extern "C" void kernel_launch(void* const* d_in, const int* in_sizes, int n_in,
                              void* d_out, int out_size)
{
    const float* X  = (const float*)d_in[0];
    const float* Wq = (const float*)d_in[2];
    const float* bq = (const float*)d_in[3];
    const float* Wk = (const float*)d_in[4];
    const float* bk = (const float*)d_in[5];
    const float* Wv = (const float*)d_in[6];
    const float* bv = (const float*)d_in[7];
    const float* Wo = (const float*)d_in[8];
    float* out = (float*)d_out;

    split_all<<<N_ALL4 / 256, 256>>>(X, Wq, Wk, Wv, Wo);

    cudaFuncSetAttribute(hgemm3_k<0>, cudaFuncAttributeMaxDynamicSharedMemorySize, GEMM_SMEM);
    cudaFuncSetAttribute(hgemm3_k<1>, cudaFuncAttributeMaxDynamicSharedMemorySize, GEMM_SMEM);

    hgemm3_k<0><<<dim3(24, S_LEN / 256), 256, GEMM_SMEM>>>(bq, bk, bv, nullptr);

    rope_all<<<(ROPE_Q_N + ROPE_K_N) / 256, 256>>>();

    cudaFuncSetAttribute(attn_k, cudaFuncAttributeMaxDynamicSharedMemorySize, ATTN_SMEM);
    attn_k<<<dim3(32, NH), 128, ATTN_SMEM>>>();

    hgemm3_k<1><<<dim3(16, S_LEN / 256), 256, GEMM_SMEM>>>(nullptr, nullptr, nullptr, out);
}

// round 9
// speedup vs baseline: 1.1061x; 1.1061x over previous
#include <cuda_runtime.h>
#include <cuda_bf16.h>
#include <math.h>
#include <stdint.h>

#define S_LEN 2048
#define HID   2048
#define NH    32
#define NKV   8
#define HD    64

// ---------------------------------------------------------------------------
// Scratch (device globals)
// ---------------------------------------------------------------------------
__device__ float g_q[NH * S_LEN * HD];     // pre-RoPE Q fp32
__device__ float g_k[NKV * S_LEN * HD];    // pre-RoPE K fp32

__device__ __nv_bfloat16 g_Xh[S_LEN * HID],  g_Xl[S_LEN * HID];
__device__ __nv_bfloat16 g_Wqh[HID * HID],   g_Wql[HID * HID];
__device__ __nv_bfloat16 g_Wkh[NKV*HD*HID],  g_Wkl[NKV*HD*HID];
__device__ __nv_bfloat16 g_Wvh[NKV*HD*HID],  g_Wvl[NKV*HD*HID];
__device__ __nv_bfloat16 g_Woh[HID * HID],   g_Wol[HID * HID];
__device__ __nv_bfloat16 g_Ch[S_LEN * HID],  g_Cl[S_LEN * HID];    // attn out split

__device__ __nv_bfloat16 g_qh[NH * S_LEN * HD],  g_ql[NH * S_LEN * HD];   // post-RoPE
__device__ __nv_bfloat16 g_kh[NKV * S_LEN * HD], g_kl[NKV * S_LEN * HD];
__device__ __nv_bfloat16 g_vh[NKV * S_LEN * HD], g_vl[NKV * S_LEN * HD];

// ---------------------------------------------------------------------------
// PTX helpers (plain sm_80+ features only)
// ---------------------------------------------------------------------------
__device__ __forceinline__ uint32_t s2u(const void* p) {
    uint32_t a;
    asm("{ .reg .u64 t; cvta.to.shared.u64 t, %1; cvt.u32.u64 %0, t; }" : "=r"(a) : "l"(p));
    return a;
}

__device__ __forceinline__ void ldsm4(uint32_t* r, uint32_t addr) {
    asm volatile("ldmatrix.sync.aligned.m8n8.x4.shared.b16 {%0,%1,%2,%3}, [%4];"
                 : "=r"(r[0]), "=r"(r[1]), "=r"(r[2]), "=r"(r[3]) : "r"(addr));
}

__device__ __forceinline__ void ldsm4t(uint32_t* r, uint32_t addr) {
    asm volatile("ldmatrix.sync.aligned.m8n8.x4.trans.shared.b16 {%0,%1,%2,%3}, [%4];"
                 : "=r"(r[0]), "=r"(r[1]), "=r"(r[2]), "=r"(r[3]) : "r"(addr));
}

__device__ __forceinline__ void mma16816(float* d, uint32_t a0, uint32_t a1, uint32_t a2,
                                         uint32_t a3, uint32_t b0, uint32_t b1) {
    asm volatile(
        "mma.sync.aligned.m16n8k16.row.col.f32.bf16.bf16.f32 "
        "{%0,%1,%2,%3}, {%4,%5,%6,%7}, {%8,%9}, {%0,%1,%2,%3};"
        : "+f"(d[0]), "+f"(d[1]), "+f"(d[2]), "+f"(d[3])
        : "r"(a0), "r"(a1), "r"(a2), "r"(a3), "r"(b0), "r"(b1));
}

__device__ __forceinline__ void cpa16(uint32_t saddr, const void* g) {
    asm volatile("cp.async.cg.shared.global [%0], [%1], 16;" :: "r"(saddr), "l"(g) : "memory");
}

__device__ __forceinline__ uint32_t packbf(float lo, float hi) {
    uint32_t r;
    asm("cvt.rn.bf16x2.f32 %0, %1, %2;" : "=r"(r) : "f"(hi), "f"(lo));
    return r;
}
__device__ __forceinline__ float lo_of(uint32_t p) { return __uint_as_float(p << 16); }
__device__ __forceinline__ float hi_of(uint32_t p) { return __uint_as_float(p & 0xFFFF0000u); }

// ---------------------------------------------------------------------------
// Merged fp32 -> (bf16 hi, bf16 lo) split for all 5 inputs. One launch.
// ---------------------------------------------------------------------------
#define N_X4  1048576
#define N_WQ4 1048576
#define N_WK4 262144
#define N_WV4 262144
#define N_WO4 1048576
#define N_ALL4 (N_X4 + N_WQ4 + N_WK4 + N_WV4 + N_WO4)

__global__ __launch_bounds__(256) void split_all(const float* __restrict__ X,
                                                 const float* __restrict__ Wq,
                                                 const float* __restrict__ Wk,
                                                 const float* __restrict__ Wv,
                                                 const float* __restrict__ Wo)
{
    const int i = blockIdx.x * 256 + threadIdx.x;
    const float* src;
    __nv_bfloat16 *hi, *lo;
    int off;
    if (i < N_X4)                       { src = X;  hi = g_Xh;  lo = g_Xl;  off = i; }
    else if (i < N_X4 + N_WQ4)          { src = Wq; hi = g_Wqh; lo = g_Wql; off = i - N_X4; }
    else if (i < N_X4 + N_WQ4 + N_WK4)  { src = Wk; hi = g_Wkh; lo = g_Wkl; off = i - N_X4 - N_WQ4; }
    else if (i < N_X4 + N_WQ4 + N_WK4 + N_WV4)
                                        { src = Wv; hi = g_Wvh; lo = g_Wvl; off = i - N_X4 - N_WQ4 - N_WK4; }
    else                                { src = Wo; hi = g_Woh; lo = g_Wol; off = i - N_X4 - N_WQ4 - N_WK4 - N_WV4; }

    float4 v = ((const float4*)src)[off];
    __nv_bfloat16 h[4], l[4];
    float f[4] = {v.x, v.y, v.z, v.w};
#pragma unroll
    for (int k = 0; k < 4; ++k) {
        h[k] = __float2bfloat16(f[k]);
        l[k] = __float2bfloat16(f[k] - __bfloat162float(h[k]));
    }
    *(uint64_t*)(hi + 4 * off) = *(uint64_t*)h;
    *(uint64_t*)(lo + 4 * off) = *(uint64_t*)l;
}

// ---------------------------------------------------------------------------
// 128x128 split-bf16 HMMA GEMM, 2-stage cp.async, 4 warps x 64x64 warp tiles.
// MODE 0: fused QKV — N-space [Wq(2048) | Wk(512) | Wv(512)], grid (24, 16)
// MODE 1: O projection, grid (16, 16)
// smem: 2 stages x 4 tiles x (128 x 40 halfs) = 81920 B dynamic.
// ---------------------------------------------------------------------------
#define TILE_H 5120
#define STAGE_H (4 * TILE_H)
#define GEMM_SMEM (2 * STAGE_H * 2)

template <int MODE>
__global__ __launch_bounds__(128) void hgemm4_k(const float* __restrict__ bq,
                                                const float* __restrict__ bk,
                                                const float* __restrict__ bv,
                                                float* __restrict__ outp)
{
    extern __shared__ __nv_bfloat16 sm[];
    const int t = threadIdx.x, w = t >> 5, lane = t & 31;
    const int bm = blockIdx.y * 128;
    const int bn = blockIdx.x * 128;
    const int wm = (w >> 1) * 64;     // 0 or 64
    const int wn = (w & 1) * 64;      // 0 or 64

    const __nv_bfloat16 *Ah, *Al, *Bh, *Bl;
    const float* bias = nullptr;
    int outsel, bcol0;
    if (MODE == 0) {
        Ah = g_Xh; Al = g_Xl;
        if (bn < 2048)      { Bh = g_Wqh; Bl = g_Wql; bias = bq; outsel = 0; bcol0 = bn; }
        else if (bn < 2560) { Bh = g_Wkh; Bl = g_Wkl; bias = bk; outsel = 1; bcol0 = bn - 2048; }
        else                { Bh = g_Wvh; Bl = g_Wvl; bias = bv; outsel = 2; bcol0 = bn - 2560; }
    } else {
        Ah = g_Ch; Al = g_Cl; Bh = g_Woh; Bl = g_Wol; outsel = 3; bcol0 = bn;
    }

    const __nv_bfloat16* srcs[4] = { Ah + (size_t)bm * HID, Al + (size_t)bm * HID,
                                     Bh + (size_t)bcol0 * HID, Bl + (size_t)bcol0 * HID };

    const uint32_t sb = s2u(sm);
    const uint32_t a_r = lane & 15, a_c8 = (lane >> 4) << 3;
    const uint32_t b_r = ((lane >> 4) << 3) + (lane & 7), b_c8 = ((lane >> 3) & 1) << 3;

    float acc[4][8][4];
#pragma unroll
    for (int mi = 0; mi < 4; ++mi)
#pragma unroll
        for (int ni = 0; ni < 8; ++ni)
#pragma unroll
            for (int r = 0; r < 4; ++r) acc[mi][ni][r] = 0.0f;

#define ISSUE(ktv, stg)                                                              \
    {                                                                                \
        const int _kt = (ktv);                                                       \
        const uint32_t _sb0 = sb + (uint32_t)(stg) * (STAGE_H * 2);                  \
        _Pragma("unroll")                                                            \
        for (int i = 0; i < 16; ++i) {                                               \
            const int idx = i * 128 + t;                                             \
            const int tile = idx >> 9;                                               \
            const int rem = idx & 511;                                               \
            const int row = rem >> 2, q = rem & 3;                                   \
            cpa16(_sb0 + (uint32_t)(tile * TILE_H + row * 40 + q * 8) * 2,           \
                  srcs[tile] + (size_t)row * HID + _kt + q * 8);                     \
        }                                                                            \
        asm volatile("cp.async.commit_group;" ::: "memory");                         \
    }

    ISSUE(0, 0);

    for (int it = 0; it < HID / 32; ++it) {
        const int cur = it & 1;
        if (it < HID / 32 - 1) {
            ISSUE((it + 1) * 32, cur ^ 1);
            asm volatile("cp.async.wait_group 1;" ::: "memory");
        } else {
            asm volatile("cp.async.wait_group 0;" ::: "memory");
        }
        __syncthreads();

        const uint32_t st = sb + (uint32_t)cur * (STAGE_H * 2);
#pragma unroll
        for (int ks = 0; ks < 2; ++ks) {
            const uint32_t k0 = ks * 16;
            // B fragments (shared across all 4 mi)
            uint32_t bh[4][4], bl[4][4];
#pragma unroll
            for (int pi = 0; pi < 4; ++pi) {
                uint32_t off = ((wn + pi * 16 + b_r) * 40 + k0 + b_c8) * 2;
                ldsm4(bh[pi], st + 2 * (TILE_H * 2) + off);
                ldsm4(bl[pi], st + 3 * (TILE_H * 2) + off);
            }
#pragma unroll
            for (int mi = 0; mi < 4; ++mi) {
                uint32_t ah[4], al[4];
                uint32_t off = ((wm + mi * 16 + a_r) * 40 + k0 + a_c8) * 2;
                ldsm4(ah, st + 0 * (TILE_H * 2) + off);
                ldsm4(al, st + 1 * (TILE_H * 2) + off);
#pragma unroll
                for (int pi = 0; pi < 4; ++pi) {
#pragma unroll
                    for (int half = 0; half < 2; ++half) {
                        const int ni = pi * 2 + half;
                        const uint32_t B0 = bh[pi][half * 2], B1 = bh[pi][half * 2 + 1];
                        const uint32_t C0 = bl[pi][half * 2], C1 = bl[pi][half * 2 + 1];
                        mma16816(acc[mi][ni], ah[0], ah[1], ah[2], ah[3], B0, B1);
                        mma16816(acc[mi][ni], ah[0], ah[1], ah[2], ah[3], C0, C1);
                        mma16816(acc[mi][ni], al[0], al[1], al[2], al[3], B0, B1);
                    }
                }
            }
        }
        __syncthreads();
    }
#undef ISSUE

    // Epilogue
#pragma unroll
    for (int mi = 0; mi < 4; ++mi) {
#pragma unroll
        for (int ni = 0; ni < 8; ++ni) {
            const int lcol = wn + ni * 8 + 2 * (lane & 3);
            const int col = bcol0 + lcol;
            float b0 = 0.f, b1 = 0.f;
            if (MODE == 0) { b0 = bias[col]; b1 = bias[col + 1]; }
#pragma unroll
            for (int rr = 0; rr < 2; ++rr) {
                const int row = bm + wm + mi * 16 + (lane >> 2) + rr * 8;
                float vx = acc[mi][ni][rr * 2 + 0] + b0;
                float vy = acc[mi][ni][rr * 2 + 1] + b1;
                if (outsel == 0 || outsel == 1) {
                    const int head = col >> 6, d = col & 63;
                    float* dst = (outsel == 0) ? g_q : g_k;
                    float2 v2 = {vx, vy};
                    *(float2*)(dst + ((size_t)head * S_LEN + row) * HD + d) = v2;
                } else if (outsel == 2) {
                    const int head = col >> 6, d = col & 63;
                    uint32_t ph = packbf(vx, vy);
                    uint32_t pl = packbf(vx - lo_of(ph), vy - hi_of(ph));
                    const size_t off = ((size_t)head * S_LEN + row) * HD + d;
                    *(uint32_t*)(g_vh + off) = ph;
                    *(uint32_t*)(g_vl + off) = pl;
                } else {
                    float2 v2 = {vx, vy};
                    *(float2*)(outp + (size_t)row * HID + col) = v2;
                }
            }
        }
    }
}

// ---------------------------------------------------------------------------
// RoPE for Q and K in one launch.
// ---------------------------------------------------------------------------
#define ROPE_Q_N (NH * S_LEN * 16)
#define ROPE_K_N (NKV * S_LEN * 16)

__global__ __launch_bounds__(256) void rope_all()
{
    int idx = blockIdx.x * 256 + threadIdx.x;
    const float* srcb;
    __nv_bfloat16 *dhb, *dlb;
    if (idx < ROPE_Q_N) { srcb = g_q; dhb = g_qh; dlb = g_ql; }
    else                { srcb = g_k; dhb = g_kh; dlb = g_kl; idx -= ROPE_Q_N; }

    const int j2 = (idx & 15) * 2;
    const int s = (idx >> 4) & (S_LEN - 1);
    const int h = idx >> 15;
    const size_t base = ((size_t)h * S_LEN + s) * HD;

    const float* src = srcb + base;
    float y1[2], y2[2];
#pragma unroll
    for (int e = 0; e < 2; ++e) {
        const int j = j2 + e;
        const float inv_freq = powf(10000.0f, -((float)(2 * j)) / 64.0f);
        float sn, cs;
        sincosf((float)s * inv_freq, &sn, &cs);
        const float x1 = src[j], x2 = src[j + 32];
        y1[e] = x1 * cs - x2 * sn;
        y2[e] = x2 * cs + x1 * sn;
    }
    __nv_bfloat16* dh = dhb + base;
    __nv_bfloat16* dl = dlb + base;
    uint32_t p1 = packbf(y1[0], y1[1]);
    uint32_t p2 = packbf(y2[0], y2[1]);
    *(uint32_t*)(dh + j2) = p1;
    *(uint32_t*)(dh + j2 + 32) = p2;
    *(uint32_t*)(dl + j2) = packbf(y1[0] - lo_of(p1), y1[1] - hi_of(p1));
    *(uint32_t*)(dl + j2 + 32) = packbf(y2[0] - lo_of(p2), y2[1] - hi_of(p2));
}

// ---------------------------------------------------------------------------
// HMMA flash attention: 128-row q blocks, 4 warps x 32 rows, split K/V pipeline.
// smem: Qh(18432) Ql(18432) | K0(18432) | K1(18432) | V(18432) = 92160 B
// ---------------------------------------------------------------------------
#define TILE_B 9216
#define AT_QH 0
#define AT_QL 18432
#define AT_K0 36864
#define AT_K1 55296
#define AT_V  73728
#define ATTN_SMEM 92160

__global__ __launch_bounds__(128) void attn_k()
{
    extern __shared__ __nv_bfloat16 smb[];
    const uint32_t sb = s2u(smb);
    const int h = blockIdx.y;
    const int zz = blockIdx.x;
    const int qb = (zz & 1) ? (15 - (zz >> 1)) : (zz >> 1);   // 16 q-blocks of 128
    const int kvh = h >> 2;

    const int t = threadIdx.x, w = t >> 5, lane = t & 31;
    const size_t kvbase = (size_t)kvh * S_LEN * HD;

#define CPKV(dstoff, srch, srcl)                                                    \
    {                                                                               \
        _Pragma("unroll")                                                           \
        for (int ii = 0; ii < 8; ++ii) {                                            \
            const int tile = ii >> 2;                                               \
            const int rem = (ii & 3) * 128 + t;                                     \
            const int row = rem >> 3, ch = rem & 7;                                 \
            cpa16(sb + (dstoff) + tile * TILE_B + (row * 72 + ch * 8) * 2,          \
                  (tile ? (srcl) : (srch)) + row * 64 + ch * 8);                    \
        }                                                                           \
        asm volatile("cp.async.commit_group;" ::: "memory");                        \
    }

    CPKV(AT_K0, g_kh + kvbase, g_kl + kvbase);

    // Q tiles: 128 rows hi + lo
    {
        const __nv_bfloat16* qh = g_qh + ((size_t)h * S_LEN + (size_t)qb * 128) * HD;
        const __nv_bfloat16* ql = g_ql + ((size_t)h * S_LEN + (size_t)qb * 128) * HD;
#pragma unroll
        for (int ii = 0; ii < 8; ++ii) {
            const int i = ii * 128 + t;
            const int row = i >> 3, ch = i & 7;
            *(uint4*)((char*)smb + AT_QH + (row * 72 + ch * 8) * 2) =
                *(const uint4*)(qh + row * 64 + ch * 8);
            *(uint4*)((char*)smb + AT_QL + (row * 72 + ch * 8) * 2) =
                *(const uint4*)(ql + row * 64 + ch * 8);
        }
    }
    __syncthreads();

    const uint32_t a_r = lane & 15, a_c8 = (lane >> 4) << 3;
    const uint32_t b_r = ((lane >> 4) << 3) + (lane & 7), b_c8 = ((lane >> 3) & 1) << 3;
    uint32_t qfh[2][4][4], qfl[2][4][4];
#pragma unroll
    for (int mi = 0; mi < 2; ++mi)
#pragma unroll
        for (int ks = 0; ks < 4; ++ks) {
            uint32_t off = ((w * 32 + mi * 16 + a_r) * 72 + ks * 16 + a_c8) * 2;
            ldsm4(qfh[mi][ks], sb + AT_QH + off);
            ldsm4(qfl[mi][ks], sb + AT_QL + off);
        }

    float oacc[2][8][4];
#pragma unroll
    for (int mi = 0; mi < 2; ++mi)
#pragma unroll
        for (int nt = 0; nt < 8; ++nt)
#pragma unroll
            for (int e = 0; e < 4; ++e) oacc[mi][nt][e] = 0.0f;
    float m_i[2][2] = {{-1e30f, -1e30f}, {-1e30f, -1e30f}};
    float l_i[2][2] = {{0.0f, 0.0f}, {0.0f, 0.0f}};

    const int nkv = 2 * qb + 2;

    for (int kb = 0; kb < nkv; ++kb) {
        const uint32_t KHB = (kb & 1) ? AT_K1 : AT_K0;
        const uint32_t KLB = KHB + TILE_B;
        __syncthreads();
        {
            const size_t vb = kvbase + (size_t)kb * 64 * HD;
            CPKV(AT_V, g_vh + vb, g_vl + vb);
        }
        asm volatile("cp.async.wait_group 1;" ::: "memory");
        __syncthreads();

        // ---- S = Q K^T (3-term) ----
        float sacc[2][8][4];
#pragma unroll
        for (int mi = 0; mi < 2; ++mi)
#pragma unroll
            for (int nt = 0; nt < 8; ++nt)
#pragma unroll
                for (int e = 0; e < 4; ++e) sacc[mi][nt][e] = 0.0f;

#pragma unroll
        for (int ks = 0; ks < 4; ++ks) {
#pragma unroll
            for (int np = 0; np < 4; ++np) {
                uint32_t BH[4], BL[4];
                uint32_t off = ((np * 16 + b_r) * 72 + ks * 16 + b_c8) * 2;
                ldsm4(BH, sb + KHB + off);
                ldsm4(BL, sb + KLB + off);
#pragma unroll
                for (int mi = 0; mi < 2; ++mi) {
#pragma unroll
                    for (int half = 0; half < 2; ++half) {
                        const int nt = np * 2 + half;
                        mma16816(sacc[mi][nt], qfh[mi][ks][0], qfh[mi][ks][1],
                                 qfh[mi][ks][2], qfh[mi][ks][3],
                                 BH[half * 2], BH[half * 2 + 1]);
                        mma16816(sacc[mi][nt], qfh[mi][ks][0], qfh[mi][ks][1],
                                 qfh[mi][ks][2], qfh[mi][ks][3],
                                 BL[half * 2], BL[half * 2 + 1]);
                        mma16816(sacc[mi][nt], qfl[mi][ks][0], qfl[mi][ks][1],
                                 qfl[mi][ks][2], qfl[mi][ks][3],
                                 BH[half * 2], BH[half * 2 + 1]);
                    }
                }
            }
        }

        if (kb < nkv - 1) {
            const size_t nb = kvbase + (size_t)(kb + 1) * 64 * HD;
            const uint32_t nstage = (kb & 1) ? AT_K0 : AT_K1;
            CPKV(nstage, g_kh + nb, g_kl + nb);
        }

        // ---- online softmax ----
        const bool diag = (kb >= 2 * qb);
        float mt[2][2] = {{-1e30f, -1e30f}, {-1e30f, -1e30f}};
#pragma unroll
        for (int mi = 0; mi < 2; ++mi) {
            const int grow = qb * 128 + w * 32 + mi * 16 + (lane >> 2);
#pragma unroll
            for (int nt = 0; nt < 8; ++nt) {
#pragma unroll
                for (int e = 0; e < 4; ++e) {
                    float v = sacc[mi][nt][e] * 0.125f;
                    v = fminf(fmaxf(v, -50.0f), 50.0f);
                    if (diag) {
                        const int col = kb * 64 + nt * 8 + 2 * (lane & 3) + (e & 1);
                        const int row = grow + (e >> 1) * 8;
                        if (col > row) v = -1e30f;
                    }
                    sacc[mi][nt][e] = v;
                    mt[mi][e >> 1] = fmaxf(mt[mi][e >> 1], v);
                }
            }
        }
#pragma unroll
        for (int o = 1; o < 4; o <<= 1)
#pragma unroll
            for (int mi = 0; mi < 2; ++mi) {
                mt[mi][0] = fmaxf(mt[mi][0], __shfl_xor_sync(0xffffffffu, mt[mi][0], o));
                mt[mi][1] = fmaxf(mt[mi][1], __shfl_xor_sync(0xffffffffu, mt[mi][1], o));
            }
        float corr[2][2], rs[2][2] = {{0.0f, 0.0f}, {0.0f, 0.0f}};
#pragma unroll
        for (int mi = 0; mi < 2; ++mi)
#pragma unroll
            for (int rr = 0; rr < 2; ++rr) {
                const float mn = fmaxf(m_i[mi][rr], mt[mi][rr]);
                corr[mi][rr] = __expf(m_i[mi][rr] - mn);
                m_i[mi][rr] = mn;
            }
#pragma unroll
        for (int mi = 0; mi < 2; ++mi)
#pragma unroll
            for (int nt = 0; nt < 8; ++nt)
#pragma unroll
                for (int e = 0; e < 4; ++e) {
                    const float p = __expf(sacc[mi][nt][e] - m_i[mi][e >> 1]);
                    sacc[mi][nt][e] = p;
                    rs[mi][e >> 1] += p;
                }
#pragma unroll
        for (int o = 1; o < 4; o <<= 1)
#pragma unroll
            for (int mi = 0; mi < 2; ++mi) {
                rs[mi][0] += __shfl_xor_sync(0xffffffffu, rs[mi][0], o);
                rs[mi][1] += __shfl_xor_sync(0xffffffffu, rs[mi][1], o);
            }
#pragma unroll
        for (int mi = 0; mi < 2; ++mi)
#pragma unroll
            for (int rr = 0; rr < 2; ++rr)
                l_i[mi][rr] = l_i[mi][rr] * corr[mi][rr] + rs[mi][rr];
#pragma unroll
        for (int mi = 0; mi < 2; ++mi)
#pragma unroll
            for (int nt = 0; nt < 8; ++nt)
#pragma unroll
                for (int e = 0; e < 4; ++e) oacc[mi][nt][e] *= corr[mi][e >> 1];

        // ---- wait V, then PV ----
        if (kb < nkv - 1) asm volatile("cp.async.wait_group 1;" ::: "memory");
        else              asm volatile("cp.async.wait_group 0;" ::: "memory");
        __syncthreads();

#pragma unroll
        for (int ks = 0; ks < 4; ++ks) {
            const int L = 2 * ks, R = 2 * ks + 1;
            uint32_t ph[2][4], pl[2][4];
#pragma unroll
            for (int mi = 0; mi < 2; ++mi) {
                ph[mi][0] = packbf(sacc[mi][L][0], sacc[mi][L][1]);
                ph[mi][1] = packbf(sacc[mi][L][2], sacc[mi][L][3]);
                ph[mi][2] = packbf(sacc[mi][R][0], sacc[mi][R][1]);
                ph[mi][3] = packbf(sacc[mi][R][2], sacc[mi][R][3]);
                pl[mi][0] = packbf(sacc[mi][L][0] - lo_of(ph[mi][0]), sacc[mi][L][1] - hi_of(ph[mi][0]));
                pl[mi][1] = packbf(sacc[mi][L][2] - lo_of(ph[mi][1]), sacc[mi][L][3] - hi_of(ph[mi][1]));
                pl[mi][2] = packbf(sacc[mi][R][0] - lo_of(ph[mi][2]), sacc[mi][R][1] - hi_of(ph[mi][2]));
                pl[mi][3] = packbf(sacc[mi][R][2] - lo_of(ph[mi][3]), sacc[mi][R][3] - hi_of(ph[mi][3]));
            }
#pragma unroll
            for (int dp = 0; dp < 4; ++dp) {
                uint32_t VH4[4], VL4[4];
                uint32_t voff = ((ks * 16 + (lane & 7) + ((lane >> 3) & 1) * 8) * 72
                                 + dp * 16 + ((lane >> 4) << 3)) * 2;
                ldsm4t(VH4, sb + AT_V + voff);
                ldsm4t(VL4, sb + AT_V + TILE_B + voff);
#pragma unroll
                for (int mi = 0; mi < 2; ++mi) {
#pragma unroll
                    for (int half = 0; half < 2; ++half) {
                        const int nt = dp * 2 + half;
                        mma16816(oacc[mi][nt], ph[mi][0], ph[mi][1], ph[mi][2], ph[mi][3],
                                 VH4[half * 2], VH4[half * 2 + 1]);
                        mma16816(oacc[mi][nt], ph[mi][0], ph[mi][1], ph[mi][2], ph[mi][3],
                                 VL4[half * 2], VL4[half * 2 + 1]);
                        mma16816(oacc[mi][nt], pl[mi][0], pl[mi][1], pl[mi][2], pl[mi][3],
                                 VH4[half * 2], VH4[half * 2 + 1]);
                    }
                }
            }
        }
    }
#undef CPKV

    // ---- epilogue ----
#pragma unroll
    for (int mi = 0; mi < 2; ++mi) {
#pragma unroll
        for (int nt = 0; nt < 8; ++nt) {
#pragma unroll
            for (int rr = 0; rr < 2; ++rr) {
                const float inv = 1.0f / l_i[mi][rr];
                const float v0 = oacc[mi][nt][rr * 2 + 0] * inv;
                const float v1 = oacc[mi][nt][rr * 2 + 1] * inv;
                const int srow = qb * 128 + w * 32 + mi * 16 + (lane >> 2) + rr * 8;
                const int col = h * 64 + nt * 8 + 2 * (lane & 3);
                uint32_t ph = packbf(v0, v1);
                uint32_t pl = packbf(v0 - lo_of(ph), v1 - hi_of(ph));
                *(uint32_t*)(g_Ch + (size_t)srow * HID + col) = ph;
                *(uint32_t*)(g_Cl + (size_t)srow * HID + col) = pl;
            }
        }
    }
}

// ---------------------------------------------------------------------------
// Launcher
// ---------------------------------------------------------------------------
extern "C" void kernel_launch(void* const* d_in, const int* in_sizes, int n_in,
                              void* d_out, int out_size)
{
    const float* X  = (const float*)d_in[0];
    const float* Wq = (const float*)d_in[2];
    const float* bq = (const float*)d_in[3];
    const float* Wk = (const float*)d_in[4];
    const float* bk = (const float*)d_in[5];
    const float* Wv = (const float*)d_in[6];
    const float* bv = (const float*)d_in[7];
    const float* Wo = (const float*)d_in[8];
    float* out = (float*)d_out;

    split_all<<<N_ALL4 / 256, 256>>>(X, Wq, Wk, Wv, Wo);

    cudaFuncSetAttribute(hgemm4_k<0>, cudaFuncAttributeMaxDynamicSharedMemorySize, GEMM_SMEM);
    cudaFuncSetAttribute(hgemm4_k<1>, cudaFuncAttributeMaxDynamicSharedMemorySize, GEMM_SMEM);

    hgemm4_k<0><<<dim3(24, S_LEN / 128), 128, GEMM_SMEM>>>(bq, bk, bv, nullptr);

    rope_all<<<(ROPE_Q_N + ROPE_K_N) / 256, 256>>>();

    cudaFuncSetAttribute(attn_k, cudaFuncAttributeMaxDynamicSharedMemorySize, ATTN_SMEM);
    attn_k<<<dim3(16, NH), 128, ATTN_SMEM>>>();

    hgemm4_k<1><<<dim3(16, S_LEN / 128), 128, GEMM_SMEM>>>(nullptr, nullptr, nullptr, out);
}

// round 10
// speedup vs baseline: 1.5952x; 1.4422x over previous
#include <cuda_runtime.h>
#include <cuda_fp16.h>
#include <math.h>
#include <stdint.h>

#define S_LEN 2048
#define HID   2048
#define NH    32
#define NKV   8
#define HD    64

// ---------------------------------------------------------------------------
// Scratch (device globals)
// ---------------------------------------------------------------------------
__device__ float g_q[NH * S_LEN * HD];     // pre-RoPE Q fp32
__device__ float g_k[NKV * S_LEN * HD];    // pre-RoPE K fp32

__device__ __half g_Xh[S_LEN * HID], g_Xl[S_LEN * HID];   // X split (fp16 hi+lo)
__device__ __half g_Wq[HID * HID];                         // weights single fp16
__device__ __half g_Wk[NKV * HD * HID];
__device__ __half g_Wv[NKV * HD * HID];
__device__ __half g_Wo[HID * HID];
__device__ __half g_Ch[S_LEN * HID], g_Cl[S_LEN * HID];    // attn out split fp16

__device__ __half g_qh[NH * S_LEN * HD], g_ql[NH * S_LEN * HD];  // post-RoPE Q split
__device__ __half g_kh[NKV * S_LEN * HD];                        // K single fp16
__device__ __half g_vh[NKV * S_LEN * HD];                        // V single fp16

// ---------------------------------------------------------------------------
// PTX helpers
// ---------------------------------------------------------------------------
__device__ __forceinline__ uint32_t s2u(const void* p) {
    uint32_t a;
    asm("{ .reg .u64 t; cvta.to.shared.u64 t, %1; cvt.u32.u64 %0, t; }" : "=r"(a) : "l"(p));
    return a;
}

__device__ __forceinline__ void ldsm4(uint32_t* r, uint32_t addr) {
    asm volatile("ldmatrix.sync.aligned.m8n8.x4.shared.b16 {%0,%1,%2,%3}, [%4];"
                 : "=r"(r[0]), "=r"(r[1]), "=r"(r[2]), "=r"(r[3]) : "r"(addr));
}

__device__ __forceinline__ void ldsm4t(uint32_t* r, uint32_t addr) {
    asm volatile("ldmatrix.sync.aligned.m8n8.x4.trans.shared.b16 {%0,%1,%2,%3}, [%4];"
                 : "=r"(r[0]), "=r"(r[1]), "=r"(r[2]), "=r"(r[3]) : "r"(addr));
}

__device__ __forceinline__ void mma16816(float* d, uint32_t a0, uint32_t a1, uint32_t a2,
                                         uint32_t a3, uint32_t b0, uint32_t b1) {
    asm volatile(
        "mma.sync.aligned.m16n8k16.row.col.f32.f16.f16.f32 "
        "{%0,%1,%2,%3}, {%4,%5,%6,%7}, {%8,%9}, {%0,%1,%2,%3};"
        : "+f"(d[0]), "+f"(d[1]), "+f"(d[2]), "+f"(d[3])
        : "r"(a0), "r"(a1), "r"(a2), "r"(a3), "r"(b0), "r"(b1));
}

__device__ __forceinline__ void cpa16(uint32_t saddr, const void* g) {
    asm volatile("cp.async.cg.shared.global [%0], [%1], 16;" :: "r"(saddr), "l"(g) : "memory");
}

// pack two fp32 -> f16x2 {lower: first arg, upper: second arg}
__device__ __forceinline__ uint32_t packhf(float lo, float hi) {
    uint32_t r;
    asm("cvt.rn.f16x2.f32 %0, %1, %2;" : "=r"(r) : "f"(hi), "f"(lo));
    return r;
}
__device__ __forceinline__ float lo_h(uint32_t p) {
    return __half2float(__ushort_as_half((unsigned short)(p & 0xFFFFu)));
}
__device__ __forceinline__ float hi_h(uint32_t p) {
    return __half2float(__ushort_as_half((unsigned short)(p >> 16)));
}

// ---------------------------------------------------------------------------
// Merged conversion: X -> fp16 hi/lo split; weights -> single fp16.
// ---------------------------------------------------------------------------
#define N_X4  1048576
#define N_WQ4 1048576
#define N_WK4 262144
#define N_WV4 262144
#define N_WO4 1048576
#define N_ALL4 (N_X4 + N_WQ4 + N_WK4 + N_WV4 + N_WO4)

__global__ __launch_bounds__(256) void split_all(const float* __restrict__ X,
                                                 const float* __restrict__ Wq,
                                                 const float* __restrict__ Wk,
                                                 const float* __restrict__ Wv,
                                                 const float* __restrict__ Wo)
{
    const int i = blockIdx.x * 256 + threadIdx.x;
    const float* src;
    __half* hi;
    int off;
    bool do_split = false;
    if (i < N_X4)                       { src = X;  hi = g_Xh; off = i; do_split = true; }
    else if (i < N_X4 + N_WQ4)          { src = Wq; hi = g_Wq; off = i - N_X4; }
    else if (i < N_X4 + N_WQ4 + N_WK4)  { src = Wk; hi = g_Wk; off = i - N_X4 - N_WQ4; }
    else if (i < N_X4 + N_WQ4 + N_WK4 + N_WV4)
                                        { src = Wv; hi = g_Wv; off = i - N_X4 - N_WQ4 - N_WK4; }
    else                                { src = Wo; hi = g_Wo; off = i - N_X4 - N_WQ4 - N_WK4 - N_WV4; }

    float4 v = ((const float4*)src)[off];
    float f[4] = {v.x, v.y, v.z, v.w};
    __half h[4];
#pragma unroll
    for (int k = 0; k < 4; ++k) h[k] = __float2half_rn(f[k]);
    *(uint64_t*)(hi + 4 * off) = *(uint64_t*)h;
    if (do_split) {
        __half l[4];
#pragma unroll
        for (int k = 0; k < 4; ++k) l[k] = __float2half_rn(f[k] - __half2float(h[k]));
        *(uint64_t*)(g_Xl + 4 * off) = *(uint64_t*)l;
    }
}

// ---------------------------------------------------------------------------
// 128x128 2-term fp16 HMMA GEMM, 2-stage cp.async.
// A = (Ah + Al), B single fp16.  8 warps, 32x64 warp tiles (r7-proven shape).
// MODE 0: fused QKV — N-space [Wq(2048) | Wk(512) | Wv(512)], grid (24, 16)
// MODE 1: O projection, grid (16, 16)
// smem stage: Ah(128x40) | Al(128x40) | B(128x40) = 3 x 5120 halfs; 2 stages.
// ---------------------------------------------------------------------------
#define TILE_H 5120
#define STAGE_H (3 * TILE_H)
#define GEMM_SMEM (2 * STAGE_H * 2)   // 61440 B

template <int MODE>
__global__ __launch_bounds__(256) void hgemm5_k(const float* __restrict__ bq,
                                                const float* __restrict__ bk,
                                                const float* __restrict__ bv,
                                                float* __restrict__ outp)
{
    extern __shared__ __half sm[];
    const int t = threadIdx.x, w = t >> 5, lane = t & 31;
    const int bm = blockIdx.y * 128;
    const int bn = blockIdx.x * 128;
    const int wm = (w & 3) * 32, wn = (w >> 2) * 64;

    const __half *Ah, *Al, *B;
    const float* bias = nullptr;
    int outsel, bcol0;
    if (MODE == 0) {
        Ah = g_Xh; Al = g_Xl;
        if (bn < 2048)      { B = g_Wq; bias = bq; outsel = 0; bcol0 = bn; }
        else if (bn < 2560) { B = g_Wk; bias = bk; outsel = 1; bcol0 = bn - 2048; }
        else                { B = g_Wv; bias = bv; outsel = 2; bcol0 = bn - 2560; }
    } else {
        Ah = g_Ch; Al = g_Cl; B = g_Wo; outsel = 3; bcol0 = bn;
    }

    const __half* srcs[3] = { Ah + (size_t)bm * HID, Al + (size_t)bm * HID,
                              B + (size_t)bcol0 * HID };

    const uint32_t sb = s2u(sm);
    const uint32_t a_r = lane & 15, a_c8 = (lane >> 4) << 3;
    const uint32_t b_r = ((lane >> 4) << 3) + (lane & 7), b_c8 = ((lane >> 3) & 1) << 3;

    float acc[2][8][4];
#pragma unroll
    for (int mi = 0; mi < 2; ++mi)
#pragma unroll
        for (int ni = 0; ni < 8; ++ni)
#pragma unroll
            for (int r = 0; r < 4; ++r) acc[mi][ni][r] = 0.0f;

#define ISSUE(ktv, stg)                                                              \
    {                                                                                \
        const int _kt = (ktv);                                                       \
        const uint32_t _sb0 = sb + (uint32_t)(stg) * (STAGE_H * 2);                  \
        _Pragma("unroll")                                                            \
        for (int i = 0; i < 6; ++i) {                                                \
            const int idx = i * 256 + t;                                             \
            const int tile = idx >> 9;                                               \
            const int rem = idx & 511;                                               \
            const int row = rem >> 2, q = rem & 3;                                   \
            cpa16(_sb0 + (uint32_t)(tile * TILE_H + row * 40 + q * 8) * 2,           \
                  srcs[tile] + (size_t)row * HID + _kt + q * 8);                     \
        }                                                                            \
        asm volatile("cp.async.commit_group;" ::: "memory");                         \
    }

    ISSUE(0, 0);

    for (int it = 0; it < HID / 32; ++it) {
        const int cur = it & 1;
        if (it < HID / 32 - 1) {
            ISSUE((it + 1) * 32, cur ^ 1);
            asm volatile("cp.async.wait_group 1;" ::: "memory");
        } else {
            asm volatile("cp.async.wait_group 0;" ::: "memory");
        }
        __syncthreads();

        const uint32_t st = sb + (uint32_t)cur * (STAGE_H * 2);
#pragma unroll
        for (int ks = 0; ks < 2; ++ks) {
            const uint32_t k0 = ks * 16;
            uint32_t bf[4][4];
#pragma unroll
            for (int pi = 0; pi < 4; ++pi) {
                uint32_t off = ((wn + pi * 16 + b_r) * 40 + k0 + b_c8) * 2;
                ldsm4(bf[pi], st + 2 * (TILE_H * 2) + off);
            }
#pragma unroll
            for (int mi = 0; mi < 2; ++mi) {
                uint32_t ah[4], al[4];
                uint32_t off = ((wm + mi * 16 + a_r) * 40 + k0 + a_c8) * 2;
                ldsm4(ah, st + 0 * (TILE_H * 2) + off);
                ldsm4(al, st + 1 * (TILE_H * 2) + off);
#pragma unroll
                for (int pi = 0; pi < 4; ++pi) {
#pragma unroll
                    for (int half = 0; half < 2; ++half) {
                        const int ni = pi * 2 + half;
                        const uint32_t B0 = bf[pi][half * 2], B1 = bf[pi][half * 2 + 1];
                        mma16816(acc[mi][ni], ah[0], ah[1], ah[2], ah[3], B0, B1);
                        mma16816(acc[mi][ni], al[0], al[1], al[2], al[3], B0, B1);
                    }
                }
            }
        }
        __syncthreads();
    }
#undef ISSUE

    // Epilogue
#pragma unroll
    for (int mi = 0; mi < 2; ++mi) {
#pragma unroll
        for (int ni = 0; ni < 8; ++ni) {
            const int lcol = wn + ni * 8 + 2 * (lane & 3);
            const int col = bcol0 + lcol;
            float b0 = 0.f, b1 = 0.f;
            if (MODE == 0) { b0 = bias[col]; b1 = bias[col + 1]; }
#pragma unroll
            for (int rr = 0; rr < 2; ++rr) {
                const int row = bm + wm + mi * 16 + (lane >> 2) + rr * 8;
                float vx = acc[mi][ni][rr * 2 + 0] + b0;
                float vy = acc[mi][ni][rr * 2 + 1] + b1;
                if (outsel == 0 || outsel == 1) {
                    const int head = col >> 6, d = col & 63;
                    float* dst = (outsel == 0) ? g_q : g_k;
                    float2 v2 = {vx, vy};
                    *(float2*)(dst + ((size_t)head * S_LEN + row) * HD + d) = v2;
                } else if (outsel == 2) {
                    const int head = col >> 6, d = col & 63;
                    *(uint32_t*)(g_vh + ((size_t)head * S_LEN + row) * HD + d) = packhf(vx, vy);
                } else {
                    float2 v2 = {vx, vy};
                    *(float2*)(outp + (size_t)row * HID + col) = v2;
                }
            }
        }
    }
}

// ---------------------------------------------------------------------------
// RoPE: Q -> fp16 hi/lo split; K -> single fp16.
// ---------------------------------------------------------------------------
#define ROPE_Q_N (NH * S_LEN * 16)
#define ROPE_K_N (NKV * S_LEN * 16)

__global__ __launch_bounds__(256) void rope_all()
{
    int idx = blockIdx.x * 256 + threadIdx.x;
    const bool isQ = (idx < ROPE_Q_N);
    if (!isQ) idx -= ROPE_Q_N;

    const int j2 = (idx & 15) * 2;
    const int s = (idx >> 4) & (S_LEN - 1);
    const int h = idx >> 15;
    const size_t base = ((size_t)h * S_LEN + s) * HD;

    const float* src = (isQ ? g_q : g_k) + base;
    float y1[2], y2[2];
#pragma unroll
    for (int e = 0; e < 2; ++e) {
        const int j = j2 + e;
        const float inv_freq = powf(10000.0f, -((float)(2 * j)) / 64.0f);
        float sn, cs;
        sincosf((float)s * inv_freq, &sn, &cs);
        const float x1 = src[j], x2 = src[j + 32];
        y1[e] = x1 * cs - x2 * sn;
        y2[e] = x2 * cs + x1 * sn;
    }
    const uint32_t p1 = packhf(y1[0], y1[1]);
    const uint32_t p2 = packhf(y2[0], y2[1]);
    if (isQ) {
        *(uint32_t*)(g_qh + base + j2) = p1;
        *(uint32_t*)(g_qh + base + j2 + 32) = p2;
        *(uint32_t*)(g_ql + base + j2) = packhf(y1[0] - lo_h(p1), y1[1] - hi_h(p1));
        *(uint32_t*)(g_ql + base + j2 + 32) = packhf(y2[0] - lo_h(p2), y2[1] - hi_h(p2));
    } else {
        *(uint32_t*)(g_kh + base + j2) = p1;
        *(uint32_t*)(g_kh + base + j2 + 32) = p2;
    }
}

// ---------------------------------------------------------------------------
// HMMA flash attention, 2-term fp16: Q split (register), K single, V single,
// P split in-register. Split K/V cp.async pipeline (r7 discipline).
// smem: Qh(9216) Ql(9216) | K0(9216) | K1(9216) | V(9216) = 46080 B
// ---------------------------------------------------------------------------
#define TILE_B 9216
#define AT_QH 0
#define AT_QL 9216
#define AT_K0 18432
#define AT_K1 27648
#define AT_V  36864
#define ATTN_SMEM 46080

__global__ __launch_bounds__(128, 3) void attn_k()
{
    extern __shared__ __half smb[];
    const uint32_t sb = s2u(smb);
    const int h = blockIdx.y;
    const int zz = blockIdx.x;
    const int qb = (zz & 1) ? (31 - (zz >> 1)) : (zz >> 1);
    const int kvh = h >> 2;

    const int t = threadIdx.x, w = t >> 5, lane = t & 31;
    const size_t kvbase = (size_t)kvh * S_LEN * HD;

    // copy one 64x64 fp16 tile via cp.async: 4 uint4 per thread
#define CPT(dstoff, src)                                                            \
    {                                                                               \
        _Pragma("unroll")                                                           \
        for (int ii = 0; ii < 4; ++ii) {                                            \
            const int rem = ii * 128 + t;                                           \
            const int row = rem >> 3, ch = rem & 7;                                 \
            cpa16(sb + (dstoff) + (row * 72 + ch * 8) * 2,                          \
                  (src) + row * 64 + ch * 8);                                       \
        }                                                                           \
        asm volatile("cp.async.commit_group;" ::: "memory");                        \
    }

    CPT(AT_K0, g_kh + kvbase);

    // Q tiles (plain loads, hi + lo)
    {
        const __half* qh = g_qh + ((size_t)h * S_LEN + (size_t)qb * 64) * HD;
        const __half* ql = g_ql + ((size_t)h * S_LEN + (size_t)qb * 64) * HD;
#pragma unroll
        for (int ii = 0; ii < 4; ++ii) {
            const int i = ii * 128 + t;
            const int row = i >> 3, ch = i & 7;
            *(uint4*)((char*)smb + AT_QH + (row * 72 + ch * 8) * 2) =
                *(const uint4*)(qh + row * 64 + ch * 8);
            *(uint4*)((char*)smb + AT_QL + (row * 72 + ch * 8) * 2) =
                *(const uint4*)(ql + row * 64 + ch * 8);
        }
    }
    __syncthreads();

    const uint32_t a_r = lane & 15, a_c8 = (lane >> 4) << 3;
    const uint32_t b_r = ((lane >> 4) << 3) + (lane & 7), b_c8 = ((lane >> 3) & 1) << 3;
    uint32_t qfh[4][4], qfl[4][4];
#pragma unroll
    for (int ks = 0; ks < 4; ++ks) {
        uint32_t off = ((w * 16 + a_r) * 72 + ks * 16 + a_c8) * 2;
        ldsm4(qfh[ks], sb + AT_QH + off);
        ldsm4(qfl[ks], sb + AT_QL + off);
    }

    float oacc[8][4];
#pragma unroll
    for (int nt = 0; nt < 8; ++nt)
#pragma unroll
        for (int e = 0; e < 4; ++e) oacc[nt][e] = 0.0f;
    float m_i[2] = {-1e30f, -1e30f}, l_i[2] = {0.0f, 0.0f};

    const int grow0 = qb * 64 + w * 16 + (lane >> 2);

    for (int kb = 0; kb <= qb; ++kb) {
        const uint32_t KHB = (kb & 1) ? AT_K1 : AT_K0;
        __syncthreads();
        CPT(AT_V, g_vh + kvbase + (size_t)kb * 64 * HD);      // V group (newest)
        asm volatile("cp.async.wait_group 1;" ::: "memory");  // K(kb) arrived
        __syncthreads();

        // ---- S = Q K^T (2-term) ----
        float sacc[8][4];
#pragma unroll
        for (int nt = 0; nt < 8; ++nt)
#pragma unroll
            for (int e = 0; e < 4; ++e) sacc[nt][e] = 0.0f;

#pragma unroll
        for (int ks = 0; ks < 4; ++ks) {
#pragma unroll
            for (int np = 0; np < 4; ++np) {
                uint32_t BH[4];
                uint32_t off = ((np * 16 + b_r) * 72 + ks * 16 + b_c8) * 2;
                ldsm4(BH, sb + KHB + off);
#pragma unroll
                for (int half = 0; half < 2; ++half) {
                    const int nt = np * 2 + half;
                    mma16816(sacc[nt], qfh[ks][0], qfh[ks][1], qfh[ks][2], qfh[ks][3],
                             BH[half * 2], BH[half * 2 + 1]);
                    mma16816(sacc[nt], qfl[ks][0], qfl[ks][1], qfl[ks][2], qfl[ks][3],
                             BH[half * 2], BH[half * 2 + 1]);
                }
            }
        }

        if (kb < qb) {
            const uint32_t nstage = (kb & 1) ? AT_K0 : AT_K1;
            CPT(nstage, g_kh + kvbase + (size_t)(kb + 1) * 64 * HD);
        }

        // ---- online softmax ----
        const bool diag = (kb == qb);
        float mt[2] = {-1e30f, -1e30f};
#pragma unroll
        for (int nt = 0; nt < 8; ++nt) {
#pragma unroll
            for (int e = 0; e < 4; ++e) {
                float v = sacc[nt][e] * 0.125f;
                v = fminf(fmaxf(v, -50.0f), 50.0f);
                if (diag) {
                    const int col = kb * 64 + nt * 8 + 2 * (lane & 3) + (e & 1);
                    const int row = grow0 + (e >> 1) * 8;
                    if (col > row) v = -1e30f;
                }
                sacc[nt][e] = v;
                mt[e >> 1] = fmaxf(mt[e >> 1], v);
            }
        }
#pragma unroll
        for (int o = 1; o < 4; o <<= 1) {
            mt[0] = fmaxf(mt[0], __shfl_xor_sync(0xffffffffu, mt[0], o));
            mt[1] = fmaxf(mt[1], __shfl_xor_sync(0xffffffffu, mt[1], o));
        }
        float corr[2], rs[2] = {0.0f, 0.0f};
#pragma unroll
        for (int rr = 0; rr < 2; ++rr) {
            const float mn = fmaxf(m_i[rr], mt[rr]);
            corr[rr] = __expf(m_i[rr] - mn);
            m_i[rr] = mn;
        }
#pragma unroll
        for (int nt = 0; nt < 8; ++nt)
#pragma unroll
            for (int e = 0; e < 4; ++e) {
                const float p = __expf(sacc[nt][e] - m_i[e >> 1]);
                sacc[nt][e] = p;
                rs[e >> 1] += p;
            }
#pragma unroll
        for (int o = 1; o < 4; o <<= 1) {
            rs[0] += __shfl_xor_sync(0xffffffffu, rs[0], o);
            rs[1] += __shfl_xor_sync(0xffffffffu, rs[1], o);
        }
#pragma unroll
        for (int rr = 0; rr < 2; ++rr) l_i[rr] = l_i[rr] * corr[rr] + rs[rr];
#pragma unroll
        for (int nt = 0; nt < 8; ++nt)
#pragma unroll
            for (int e = 0; e < 4; ++e) oacc[nt][e] *= corr[e >> 1];

        // ---- wait V, then PV (2-term: P split, V single) ----
        if (kb < qb) asm volatile("cp.async.wait_group 1;" ::: "memory");
        else         asm volatile("cp.async.wait_group 0;" ::: "memory");
        __syncthreads();

#pragma unroll
        for (int ks = 0; ks < 4; ++ks) {
            const int L = 2 * ks, R = 2 * ks + 1;
            uint32_t ph[4], pl[4];
            ph[0] = packhf(sacc[L][0], sacc[L][1]);
            ph[1] = packhf(sacc[L][2], sacc[L][3]);
            ph[2] = packhf(sacc[R][0], sacc[R][1]);
            ph[3] = packhf(sacc[R][2], sacc[R][3]);
            pl[0] = packhf(sacc[L][0] - lo_h(ph[0]), sacc[L][1] - hi_h(ph[0]));
            pl[1] = packhf(sacc[L][2] - lo_h(ph[1]), sacc[L][3] - hi_h(ph[1]));
            pl[2] = packhf(sacc[R][0] - lo_h(ph[2]), sacc[R][1] - hi_h(ph[2]));
            pl[3] = packhf(sacc[R][2] - lo_h(ph[3]), sacc[R][3] - hi_h(ph[3]));
#pragma unroll
            for (int dp = 0; dp < 4; ++dp) {
                uint32_t VH4[4];
                uint32_t voff = ((ks * 16 + (lane & 7) + ((lane >> 3) & 1) * 8) * 72
                                 + dp * 16 + ((lane >> 4) << 3)) * 2;
                ldsm4t(VH4, sb + AT_V + voff);
#pragma unroll
                for (int half = 0; half < 2; ++half) {
                    const int nt = dp * 2 + half;
                    mma16816(oacc[nt], ph[0], ph[1], ph[2], ph[3],
                             VH4[half * 2], VH4[half * 2 + 1]);
                    mma16816(oacc[nt], pl[0], pl[1], pl[2], pl[3],
                             VH4[half * 2], VH4[half * 2 + 1]);
                }
            }
        }
    }
#undef CPT

    // ---- epilogue: normalize, fp16 split, store ----
    const float inv0 = 1.0f / l_i[0], inv1 = 1.0f / l_i[1];
#pragma unroll
    for (int nt = 0; nt < 8; ++nt) {
#pragma unroll
        for (int rr = 0; rr < 2; ++rr) {
            const float inv = rr ? inv1 : inv0;
            const float v0 = oacc[nt][rr * 2 + 0] * inv;
            const float v1 = oacc[nt][rr * 2 + 1] * inv;
            const int srow = qb * 64 + w * 16 + (lane >> 2) + rr * 8;
            const int col = h * 64 + nt * 8 + 2 * (lane & 3);
            const uint32_t ph = packhf(v0, v1);
            const uint32_t pl = packhf(v0 - lo_h(ph), v1 - hi_h(ph));
            *(uint32_t*)(g_Ch + (size_t)srow * HID + col) = ph;
            *(uint32_t*)(g_Cl + (size_t)srow * HID + col) = pl;
        }
    }
}

// ---------------------------------------------------------------------------
// Launcher
// ---------------------------------------------------------------------------
extern "C" void kernel_launch(void* const* d_in, const int* in_sizes, int n_in,
                              void* d_out, int out_size)
{
    const float* X  = (const float*)d_in[0];
    const float* Wq = (const float*)d_in[2];
    const float* bq = (const float*)d_in[3];
    const float* Wk = (const float*)d_in[4];
    const float* bk = (const float*)d_in[5];
    const float* Wv = (const float*)d_in[6];
    const float* bv = (const float*)d_in[7];
    const float* Wo = (const float*)d_in[8];
    float* out = (float*)d_out;

    split_all<<<N_ALL4 / 256, 256>>>(X, Wq, Wk, Wv, Wo);

    cudaFuncSetAttribute(hgemm5_k<0>, cudaFuncAttributeMaxDynamicSharedMemorySize, GEMM_SMEM);
    cudaFuncSetAttribute(hgemm5_k<1>, cudaFuncAttributeMaxDynamicSharedMemorySize, GEMM_SMEM);

    hgemm5_k<0><<<dim3(24, S_LEN / 128), 256, GEMM_SMEM>>>(bq, bk, bv, nullptr);

    rope_all<<<(ROPE_Q_N + ROPE_K_N) / 256, 256>>>();

    cudaFuncSetAttribute(attn_k, cudaFuncAttributeMaxDynamicSharedMemorySize, ATTN_SMEM);
    attn_k<<<dim3(32, NH), 128, ATTN_SMEM>>>();

    hgemm5_k<1><<<dim3(16, S_LEN / 128), 256, GEMM_SMEM>>>(nullptr, nullptr, nullptr, out);
}

// round 11
// speedup vs baseline: 1.8794x; 1.1782x over previous
#include <cuda_runtime.h>
#include <cuda_fp16.h>
#include <math.h>
#include <stdint.h>

#define S_LEN 2048
#define HID   2048
#define NH    32
#define NKV   8
#define HD    64

// ---------------------------------------------------------------------------
// Scratch (device globals)
// ---------------------------------------------------------------------------
__device__ float g_q[NH * S_LEN * HD];     // pre-RoPE Q fp32
__device__ float g_k[NKV * S_LEN * HD];    // pre-RoPE K fp32

__device__ __half g_Xh[S_LEN * HID], g_Xl[S_LEN * HID];   // X split (fp16 hi+lo)
__device__ __half g_Wq[HID * HID];                         // weights single fp16
__device__ __half g_Wk[NKV * HD * HID];
__device__ __half g_Wv[NKV * HD * HID];
__device__ __half g_Wo[HID * HID];
__device__ __half g_Ch[S_LEN * HID];                       // attn out single fp16

__device__ __half g_qh[NH * S_LEN * HD], g_ql[NH * S_LEN * HD];  // post-RoPE Q split
__device__ __half g_kh[NKV * S_LEN * HD];                        // K single fp16
__device__ __half g_vh[NKV * S_LEN * HD];                        // V single fp16

// ---------------------------------------------------------------------------
// PTX helpers
// ---------------------------------------------------------------------------
__device__ __forceinline__ uint32_t s2u(const void* p) {
    uint32_t a;
    asm("{ .reg .u64 t; cvta.to.shared.u64 t, %1; cvt.u32.u64 %0, t; }" : "=r"(a) : "l"(p));
    return a;
}

__device__ __forceinline__ void ldsm4(uint32_t* r, uint32_t addr) {
    asm volatile("ldmatrix.sync.aligned.m8n8.x4.shared.b16 {%0,%1,%2,%3}, [%4];"
                 : "=r"(r[0]), "=r"(r[1]), "=r"(r[2]), "=r"(r[3]) : "r"(addr));
}

__device__ __forceinline__ void ldsm4t(uint32_t* r, uint32_t addr) {
    asm volatile("ldmatrix.sync.aligned.m8n8.x4.trans.shared.b16 {%0,%1,%2,%3}, [%4];"
                 : "=r"(r[0]), "=r"(r[1]), "=r"(r[2]), "=r"(r[3]) : "r"(addr));
}

__device__ __forceinline__ void mma16816(float* d, uint32_t a0, uint32_t a1, uint32_t a2,
                                         uint32_t a3, uint32_t b0, uint32_t b1) {
    asm volatile(
        "mma.sync.aligned.m16n8k16.row.col.f32.f16.f16.f32 "
        "{%0,%1,%2,%3}, {%4,%5,%6,%7}, {%8,%9}, {%0,%1,%2,%3};"
        : "+f"(d[0]), "+f"(d[1]), "+f"(d[2]), "+f"(d[3])
        : "r"(a0), "r"(a1), "r"(a2), "r"(a3), "r"(b0), "r"(b1));
}

__device__ __forceinline__ void cpa16(uint32_t saddr, const void* g) {
    asm volatile("cp.async.cg.shared.global [%0], [%1], 16;" :: "r"(saddr), "l"(g) : "memory");
}

__device__ __forceinline__ uint32_t packhf(float lo, float hi) {
    uint32_t r;
    asm("cvt.rn.f16x2.f32 %0, %1, %2;" : "=r"(r) : "f"(hi), "f"(lo));
    return r;
}
__device__ __forceinline__ float lo_h(uint32_t p) {
    return __half2float(__ushort_as_half((unsigned short)(p & 0xFFFFu)));
}
__device__ __forceinline__ float hi_h(uint32_t p) {
    return __half2float(__ushort_as_half((unsigned short)(p >> 16)));
}

// ---------------------------------------------------------------------------
// Merged conversion: X -> fp16 hi/lo split; weights -> single fp16.
// ---------------------------------------------------------------------------
#define N_X4  1048576
#define N_WQ4 1048576
#define N_WK4 262144
#define N_WV4 262144
#define N_WO4 1048576
#define N_ALL4 (N_X4 + N_WQ4 + N_WK4 + N_WV4 + N_WO4)

__global__ __launch_bounds__(256) void split_all(const float* __restrict__ X,
                                                 const float* __restrict__ Wq,
                                                 const float* __restrict__ Wk,
                                                 const float* __restrict__ Wv,
                                                 const float* __restrict__ Wo)
{
    const int i = blockIdx.x * 256 + threadIdx.x;
    const float* src;
    __half* hi;
    int off;
    bool do_split = false;
    if (i < N_X4)                       { src = X;  hi = g_Xh; off = i; do_split = true; }
    else if (i < N_X4 + N_WQ4)          { src = Wq; hi = g_Wq; off = i - N_X4; }
    else if (i < N_X4 + N_WQ4 + N_WK4)  { src = Wk; hi = g_Wk; off = i - N_X4 - N_WQ4; }
    else if (i < N_X4 + N_WQ4 + N_WK4 + N_WV4)
                                        { src = Wv; hi = g_Wv; off = i - N_X4 - N_WQ4 - N_WK4; }
    else                                { src = Wo; hi = g_Wo; off = i - N_X4 - N_WQ4 - N_WK4 - N_WV4; }

    float4 v = ((const float4*)src)[off];
    float f[4] = {v.x, v.y, v.z, v.w};
    __half h[4];
#pragma unroll
    for (int k = 0; k < 4; ++k) h[k] = __float2half_rn(f[k]);
    *(uint64_t*)(hi + 4 * off) = *(uint64_t*)h;
    if (do_split) {
        __half l[4];
#pragma unroll
        for (int k = 0; k < 4; ++k) l[k] = __float2half_rn(f[k] - __half2float(h[k]));
        *(uint64_t*)(g_Xl + 4 * off) = *(uint64_t*)l;
    }
}

// ---------------------------------------------------------------------------
// 128x128 fp16 HMMA GEMM, K-tile 64, 2-stage cp.async.
// MODE 0 (fused QKV): A = Xh+Xl (2-term), B single.  3 tiles/stage, 110.6 KB.
// MODE 1 (O proj):    A = Ch (1-term),   B = Wo.     2 tiles/stage,  73.7 KB.
// 8 warps, 32x64 warp tiles. Tile = 128 rows x 72 halfs (64 data + 8 pad).
// ---------------------------------------------------------------------------
#define T64_H 9216                  // halfs per tile (128*72)
#define T64_B (T64_H * 2)           // 18432 bytes

template <int MODE>
__global__ __launch_bounds__(256) void hgemm6_k(const float* __restrict__ bq,
                                                const float* __restrict__ bk,
                                                const float* __restrict__ bv,
                                                float* __restrict__ outp)
{
    constexpr int NTERMS = (MODE == 0) ? 2 : 1;
    constexpr int NTILES = NTERMS + 1;
    constexpr uint32_t STAGE_B = NTILES * T64_B;
    constexpr uint32_t BOFF = NTERMS * T64_B;   // B tile byte offset in stage

    extern __shared__ __half sm[];
    const int t = threadIdx.x, w = t >> 5, lane = t & 31;
    const int bm = blockIdx.y * 128;
    const int bn = blockIdx.x * 128;
    const int wm = (w & 3) * 32, wn = (w >> 2) * 64;

    const __half* srcs[NTILES];
    const float* bias = nullptr;
    int outsel, bcol0;
    if (MODE == 0) {
        const __half* B;
        if (bn < 2048)      { B = g_Wq; bias = bq; outsel = 0; bcol0 = bn; }
        else if (bn < 2560) { B = g_Wk; bias = bk; outsel = 1; bcol0 = bn - 2048; }
        else                { B = g_Wv; bias = bv; outsel = 2; bcol0 = bn - 2560; }
        srcs[0] = g_Xh + (size_t)bm * HID;
        srcs[1] = g_Xl + (size_t)bm * HID;
        srcs[NTERMS] = B + (size_t)bcol0 * HID;
    } else {
        outsel = 3; bcol0 = bn;
        srcs[0] = g_Ch + (size_t)bm * HID;
        srcs[NTERMS] = g_Wo + (size_t)bcol0 * HID;
    }

    const uint32_t sb = s2u(sm);
    const uint32_t a_r = lane & 15, a_c8 = (lane >> 4) << 3;
    const uint32_t b_r = ((lane >> 4) << 3) + (lane & 7), b_c8 = ((lane >> 3) & 1) << 3;

    float acc[2][8][4];
#pragma unroll
    for (int mi = 0; mi < 2; ++mi)
#pragma unroll
        for (int ni = 0; ni < 8; ++ni)
#pragma unroll
            for (int r = 0; r < 4; ++r) acc[mi][ni][r] = 0.0f;

    // one K-tile (64 cols) of all tiles into stage stg; 4*NTILES uint4/thread
#define ISSUE(ktv, stg)                                                              \
    {                                                                                \
        const int _kt = (ktv);                                                       \
        const uint32_t _sb0 = sb + (uint32_t)(stg) * STAGE_B;                        \
        _Pragma("unroll")                                                            \
        for (int i = 0; i < 4 * NTILES; ++i) {                                       \
            const int idx = i * 256 + t;                                             \
            const int tile = idx >> 10;                                              \
            const int rem = idx & 1023;                                              \
            const int row = rem >> 3, ch = rem & 7;                                  \
            cpa16(_sb0 + (uint32_t)(tile * T64_H + row * 72 + ch * 8) * 2,           \
                  srcs[tile] + (size_t)row * HID + _kt + ch * 8);                    \
        }                                                                            \
        asm volatile("cp.async.commit_group;" ::: "memory");                         \
    }

    ISSUE(0, 0);

    for (int it = 0; it < HID / 64; ++it) {
        const int cur = it & 1;
        if (it < HID / 64 - 1) {
            ISSUE((it + 1) * 64, cur ^ 1);
            asm volatile("cp.async.wait_group 1;" ::: "memory");
        } else {
            asm volatile("cp.async.wait_group 0;" ::: "memory");
        }
        __syncthreads();

        const uint32_t st = sb + (uint32_t)cur * STAGE_B;
#pragma unroll
        for (int ks = 0; ks < 4; ++ks) {
            const uint32_t k0 = ks * 16;
            uint32_t bf[4][4];
#pragma unroll
            for (int pi = 0; pi < 4; ++pi) {
                uint32_t off = ((wn + pi * 16 + b_r) * 72 + k0 + b_c8) * 2;
                ldsm4(bf[pi], st + BOFF + off);
            }
#pragma unroll
            for (int mi = 0; mi < 2; ++mi) {
                uint32_t ah[4], al[4];
                uint32_t off = ((wm + mi * 16 + a_r) * 72 + k0 + a_c8) * 2;
                ldsm4(ah, st + 0 * T64_B + off);
                if (NTERMS == 2) ldsm4(al, st + 1 * T64_B + off);
#pragma unroll
                for (int pi = 0; pi < 4; ++pi) {
#pragma unroll
                    for (int half = 0; half < 2; ++half) {
                        const int ni = pi * 2 + half;
                        const uint32_t B0 = bf[pi][half * 2], B1 = bf[pi][half * 2 + 1];
                        mma16816(acc[mi][ni], ah[0], ah[1], ah[2], ah[3], B0, B1);
                        if (NTERMS == 2)
                            mma16816(acc[mi][ni], al[0], al[1], al[2], al[3], B0, B1);
                    }
                }
            }
        }
        __syncthreads();
    }
#undef ISSUE

    // Epilogue
#pragma unroll
    for (int mi = 0; mi < 2; ++mi) {
#pragma unroll
        for (int ni = 0; ni < 8; ++ni) {
            const int lcol = wn + ni * 8 + 2 * (lane & 3);
            const int col = bcol0 + lcol;
            float b0 = 0.f, b1 = 0.f;
            if (MODE == 0) { b0 = bias[col]; b1 = bias[col + 1]; }
#pragma unroll
            for (int rr = 0; rr < 2; ++rr) {
                const int row = bm + wm + mi * 16 + (lane >> 2) + rr * 8;
                float vx = acc[mi][ni][rr * 2 + 0] + b0;
                float vy = acc[mi][ni][rr * 2 + 1] + b1;
                if (outsel == 0 || outsel == 1) {
                    const int head = col >> 6, d = col & 63;
                    float* dst = (outsel == 0) ? g_q : g_k;
                    float2 v2 = {vx, vy};
                    *(float2*)(dst + ((size_t)head * S_LEN + row) * HD + d) = v2;
                } else if (outsel == 2) {
                    const int head = col >> 6, d = col & 63;
                    *(uint32_t*)(g_vh + ((size_t)head * S_LEN + row) * HD + d) = packhf(vx, vy);
                } else {
                    float2 v2 = {vx, vy};
                    *(float2*)(outp + (size_t)row * HID + col) = v2;
                }
            }
        }
    }
}

#define GEMM_SMEM0 (2 * 3 * T64_B)   // 110592
#define GEMM_SMEM1 (2 * 2 * T64_B)   // 73728

// ---------------------------------------------------------------------------
// RoPE: Q -> fp16 hi/lo split; K -> single fp16.
// ---------------------------------------------------------------------------
#define ROPE_Q_N (NH * S_LEN * 16)
#define ROPE_K_N (NKV * S_LEN * 16)

__global__ __launch_bounds__(256) void rope_all()
{
    int idx = blockIdx.x * 256 + threadIdx.x;
    const bool isQ = (idx < ROPE_Q_N);
    if (!isQ) idx -= ROPE_Q_N;

    const int j2 = (idx & 15) * 2;
    const int s = (idx >> 4) & (S_LEN - 1);
    const int h = idx >> 15;
    const size_t base = ((size_t)h * S_LEN + s) * HD;

    const float* src = (isQ ? g_q : g_k) + base;
    float y1[2], y2[2];
#pragma unroll
    for (int e = 0; e < 2; ++e) {
        const int j = j2 + e;
        const float inv_freq = powf(10000.0f, -((float)(2 * j)) / 64.0f);
        float sn, cs;
        sincosf((float)s * inv_freq, &sn, &cs);
        const float x1 = src[j], x2 = src[j + 32];
        y1[e] = x1 * cs - x2 * sn;
        y2[e] = x2 * cs + x1 * sn;
    }
    const uint32_t p1 = packhf(y1[0], y1[1]);
    const uint32_t p2 = packhf(y2[0], y2[1]);
    if (isQ) {
        *(uint32_t*)(g_qh + base + j2) = p1;
        *(uint32_t*)(g_qh + base + j2 + 32) = p2;
        *(uint32_t*)(g_ql + base + j2) = packhf(y1[0] - lo_h(p1), y1[1] - hi_h(p1));
        *(uint32_t*)(g_ql + base + j2 + 32) = packhf(y2[0] - lo_h(p2), y2[1] - hi_h(p2));
    } else {
        *(uint32_t*)(g_kh + base + j2) = p1;
        *(uint32_t*)(g_kh + base + j2 + 32) = p2;
    }
}

// ---------------------------------------------------------------------------
// HMMA flash attention, 2-term fp16 (r10 proven, 139us). Epilogue: single-fp16 C.
// smem: Qh(9216) Ql(9216) | K0(9216) | K1(9216) | V(9216) = 46080 B
// ---------------------------------------------------------------------------
#define TILE_B 9216
#define AT_QH 0
#define AT_QL 9216
#define AT_K0 18432
#define AT_K1 27648
#define AT_V  36864
#define ATTN_SMEM 46080

__global__ __launch_bounds__(128, 3) void attn_k()
{
    extern __shared__ __half smb[];
    const uint32_t sb = s2u(smb);
    const int h = blockIdx.y;
    const int zz = blockIdx.x;
    const int qb = (zz & 1) ? (31 - (zz >> 1)) : (zz >> 1);
    const int kvh = h >> 2;

    const int t = threadIdx.x, w = t >> 5, lane = t & 31;
    const size_t kvbase = (size_t)kvh * S_LEN * HD;

#define CPT(dstoff, src)                                                            \
    {                                                                               \
        _Pragma("unroll")                                                           \
        for (int ii = 0; ii < 4; ++ii) {                                            \
            const int rem = ii * 128 + t;                                           \
            const int row = rem >> 3, ch = rem & 7;                                 \
            cpa16(sb + (dstoff) + (row * 72 + ch * 8) * 2,                          \
                  (src) + row * 64 + ch * 8);                                       \
        }                                                                           \
        asm volatile("cp.async.commit_group;" ::: "memory");                        \
    }

    CPT(AT_K0, g_kh + kvbase);

    {
        const __half* qh = g_qh + ((size_t)h * S_LEN + (size_t)qb * 64) * HD;
        const __half* ql = g_ql + ((size_t)h * S_LEN + (size_t)qb * 64) * HD;
#pragma unroll
        for (int ii = 0; ii < 4; ++ii) {
            const int i = ii * 128 + t;
            const int row = i >> 3, ch = i & 7;
            *(uint4*)((char*)smb + AT_QH + (row * 72 + ch * 8) * 2) =
                *(const uint4*)(qh + row * 64 + ch * 8);
            *(uint4*)((char*)smb + AT_QL + (row * 72 + ch * 8) * 2) =
                *(const uint4*)(ql + row * 64 + ch * 8);
        }
    }
    __syncthreads();

    const uint32_t a_r = lane & 15, a_c8 = (lane >> 4) << 3;
    const uint32_t b_r = ((lane >> 4) << 3) + (lane & 7), b_c8 = ((lane >> 3) & 1) << 3;
    uint32_t qfh[4][4], qfl[4][4];
#pragma unroll
    for (int ks = 0; ks < 4; ++ks) {
        uint32_t off = ((w * 16 + a_r) * 72 + ks * 16 + a_c8) * 2;
        ldsm4(qfh[ks], sb + AT_QH + off);
        ldsm4(qfl[ks], sb + AT_QL + off);
    }

    float oacc[8][4];
#pragma unroll
    for (int nt = 0; nt < 8; ++nt)
#pragma unroll
        for (int e = 0; e < 4; ++e) oacc[nt][e] = 0.0f;
    float m_i[2] = {-1e30f, -1e30f}, l_i[2] = {0.0f, 0.0f};

    const int grow0 = qb * 64 + w * 16 + (lane >> 2);

    for (int kb = 0; kb <= qb; ++kb) {
        const uint32_t KHB = (kb & 1) ? AT_K1 : AT_K0;
        __syncthreads();
        CPT(AT_V, g_vh + kvbase + (size_t)kb * 64 * HD);
        asm volatile("cp.async.wait_group 1;" ::: "memory");
        __syncthreads();

        float sacc[8][4];
#pragma unroll
        for (int nt = 0; nt < 8; ++nt)
#pragma unroll
            for (int e = 0; e < 4; ++e) sacc[nt][e] = 0.0f;

#pragma unroll
        for (int ks = 0; ks < 4; ++ks) {
#pragma unroll
            for (int np = 0; np < 4; ++np) {
                uint32_t BH[4];
                uint32_t off = ((np * 16 + b_r) * 72 + ks * 16 + b_c8) * 2;
                ldsm4(BH, sb + KHB + off);
#pragma unroll
                for (int half = 0; half < 2; ++half) {
                    const int nt = np * 2 + half;
                    mma16816(sacc[nt], qfh[ks][0], qfh[ks][1], qfh[ks][2], qfh[ks][3],
                             BH[half * 2], BH[half * 2 + 1]);
                    mma16816(sacc[nt], qfl[ks][0], qfl[ks][1], qfl[ks][2], qfl[ks][3],
                             BH[half * 2], BH[half * 2 + 1]);
                }
            }
        }

        if (kb < qb) {
            const uint32_t nstage = (kb & 1) ? AT_K0 : AT_K1;
            CPT(nstage, g_kh + kvbase + (size_t)(kb + 1) * 64 * HD);
        }

        const bool diag = (kb == qb);
        float mt[2] = {-1e30f, -1e30f};
#pragma unroll
        for (int nt = 0; nt < 8; ++nt) {
#pragma unroll
            for (int e = 0; e < 4; ++e) {
                float v = sacc[nt][e] * 0.125f;
                v = fminf(fmaxf(v, -50.0f), 50.0f);
                if (diag) {
                    const int col = kb * 64 + nt * 8 + 2 * (lane & 3) + (e & 1);
                    const int row = grow0 + (e >> 1) * 8;
                    if (col > row) v = -1e30f;
                }
                sacc[nt][e] = v;
                mt[e >> 1] = fmaxf(mt[e >> 1], v);
            }
        }
#pragma unroll
        for (int o = 1; o < 4; o <<= 1) {
            mt[0] = fmaxf(mt[0], __shfl_xor_sync(0xffffffffu, mt[0], o));
            mt[1] = fmaxf(mt[1], __shfl_xor_sync(0xffffffffu, mt[1], o));
        }
        float corr[2], rs[2] = {0.0f, 0.0f};
#pragma unroll
        for (int rr = 0; rr < 2; ++rr) {
            const float mn = fmaxf(m_i[rr], mt[rr]);
            corr[rr] = __expf(m_i[rr] - mn);
            m_i[rr] = mn;
        }
#pragma unroll
        for (int nt = 0; nt < 8; ++nt)
#pragma unroll
            for (int e = 0; e < 4; ++e) {
                const float p = __expf(sacc[nt][e] - m_i[e >> 1]);
                sacc[nt][e] = p;
                rs[e >> 1] += p;
            }
#pragma unroll
        for (int o = 1; o < 4; o <<= 1) {
            rs[0] += __shfl_xor_sync(0xffffffffu, rs[0], o);
            rs[1] += __shfl_xor_sync(0xffffffffu, rs[1], o);
        }
#pragma unroll
        for (int rr = 0; rr < 2; ++rr) l_i[rr] = l_i[rr] * corr[rr] + rs[rr];
#pragma unroll
        for (int nt = 0; nt < 8; ++nt)
#pragma unroll
            for (int e = 0; e < 4; ++e) oacc[nt][e] *= corr[e >> 1];

        if (kb < qb) asm volatile("cp.async.wait_group 1;" ::: "memory");
        else         asm volatile("cp.async.wait_group 0;" ::: "memory");
        __syncthreads();

#pragma unroll
        for (int ks = 0; ks < 4; ++ks) {
            const int L = 2 * ks, R = 2 * ks + 1;
            uint32_t ph[4], pl[4];
            ph[0] = packhf(sacc[L][0], sacc[L][1]);
            ph[1] = packhf(sacc[L][2], sacc[L][3]);
            ph[2] = packhf(sacc[R][0], sacc[R][1]);
            ph[3] = packhf(sacc[R][2], sacc[R][3]);
            pl[0] = packhf(sacc[L][0] - lo_h(ph[0]), sacc[L][1] - hi_h(ph[0]));
            pl[1] = packhf(sacc[L][2] - lo_h(ph[1]), sacc[L][3] - hi_h(ph[1]));
            pl[2] = packhf(sacc[R][0] - lo_h(ph[2]), sacc[R][1] - hi_h(ph[2]));
            pl[3] = packhf(sacc[R][2] - lo_h(ph[3]), sacc[R][3] - hi_h(ph[3]));
#pragma unroll
            for (int dp = 0; dp < 4; ++dp) {
                uint32_t VH4[4];
                uint32_t voff = ((ks * 16 + (lane & 7) + ((lane >> 3) & 1) * 8) * 72
                                 + dp * 16 + ((lane >> 4) << 3)) * 2;
                ldsm4t(VH4, sb + AT_V + voff);
#pragma unroll
                for (int half = 0; half < 2; ++half) {
                    const int nt = dp * 2 + half;
                    mma16816(oacc[nt], ph[0], ph[1], ph[2], ph[3],
                             VH4[half * 2], VH4[half * 2 + 1]);
                    mma16816(oacc[nt], pl[0], pl[1], pl[2], pl[3],
                             VH4[half * 2], VH4[half * 2 + 1]);
                }
            }
        }
    }
#undef CPT

    // ---- epilogue: normalize, single-fp16 store ----
    const float inv0 = 1.0f / l_i[0], inv1 = 1.0f / l_i[1];
#pragma unroll
    for (int nt = 0; nt < 8; ++nt) {
#pragma unroll
        for (int rr = 0; rr < 2; ++rr) {
            const float inv = rr ? inv1 : inv0;
            const float v0 = oacc[nt][rr * 2 + 0] * inv;
            const float v1 = oacc[nt][rr * 2 + 1] * inv;
            const int srow = qb * 64 + w * 16 + (lane >> 2) + rr * 8;
            const int col = h * 64 + nt * 8 + 2 * (lane & 3);
            *(uint32_t*)(g_Ch + (size_t)srow * HID + col) = packhf(v0, v1);
        }
    }
}

// ---------------------------------------------------------------------------
// Launcher
// ---------------------------------------------------------------------------
extern "C" void kernel_launch(void* const* d_in, const int* in_sizes, int n_in,
                              void* d_out, int out_size)
{
    const float* X  = (const float*)d_in[0];
    const float* Wq = (const float*)d_in[2];
    const float* bq = (const float*)d_in[3];
    const float* Wk = (const float*)d_in[4];
    const float* bk = (const float*)d_in[5];
    const float* Wv = (const float*)d_in[6];
    const float* bv = (const float*)d_in[7];
    const float* Wo = (const float*)d_in[8];
    float* out = (float*)d_out;

    split_all<<<N_ALL4 / 256, 256>>>(X, Wq, Wk, Wv, Wo);

    cudaFuncSetAttribute(hgemm6_k<0>, cudaFuncAttributeMaxDynamicSharedMemorySize, GEMM_SMEM0);
    cudaFuncSetAttribute(hgemm6_k<1>, cudaFuncAttributeMaxDynamicSharedMemorySize, GEMM_SMEM1);

    hgemm6_k<0><<<dim3(24, S_LEN / 128), 256, GEMM_SMEM0>>>(bq, bk, bv, nullptr);

    rope_all<<<(ROPE_Q_N + ROPE_K_N) / 256, 256>>>();

    cudaFuncSetAttribute(attn_k, cudaFuncAttributeMaxDynamicSharedMemorySize, ATTN_SMEM);
    attn_k<<<dim3(32, NH), 128, ATTN_SMEM>>>();

    hgemm6_k<1><<<dim3(16, S_LEN / 128), 256, GEMM_SMEM1>>>(nullptr, nullptr, nullptr, out);
}

// round 12
// speedup vs baseline: 1.9905x; 1.0591x over previous
#include <cuda_runtime.h>
#include <cuda_fp16.h>
#include <math.h>
#include <stdint.h>

#define S_LEN 2048
#define HID   2048
#define NH    32
#define NKV   8
#define HD    64

// ---------------------------------------------------------------------------
// Scratch (device globals)
// ---------------------------------------------------------------------------
__device__ float g_q[NH * S_LEN * HD];     // pre-RoPE Q fp32
__device__ float g_k[NKV * S_LEN * HD];    // pre-RoPE K fp32

__device__ __half g_Xh[S_LEN * HID], g_Xl[S_LEN * HID];   // X split (fp16 hi+lo)
__device__ __half g_Wq[HID * HID];                         // weights single fp16
__device__ __half g_Wk[NKV * HD * HID];
__device__ __half g_Wv[NKV * HD * HID];
__device__ __half g_Wo[HID * HID];
__device__ __half g_Ch[S_LEN * HID];                       // attn out single fp16

__device__ __half g_qh[NH * S_LEN * HD], g_ql[NH * S_LEN * HD];  // post-RoPE Q split
__device__ __half g_kh[NKV * S_LEN * HD];                        // K single fp16
__device__ __half g_vh[NKV * S_LEN * HD];                        // V single fp16

// ---------------------------------------------------------------------------
// PTX helpers
// ---------------------------------------------------------------------------
__device__ __forceinline__ uint32_t s2u(const void* p) {
    uint32_t a;
    asm("{ .reg .u64 t; cvta.to.shared.u64 t, %1; cvt.u32.u64 %0, t; }" : "=r"(a) : "l"(p));
    return a;
}

__device__ __forceinline__ void ldsm4(uint32_t* r, uint32_t addr) {
    asm volatile("ldmatrix.sync.aligned.m8n8.x4.shared.b16 {%0,%1,%2,%3}, [%4];"
                 : "=r"(r[0]), "=r"(r[1]), "=r"(r[2]), "=r"(r[3]) : "r"(addr));
}

__device__ __forceinline__ void ldsm4t(uint32_t* r, uint32_t addr) {
    asm volatile("ldmatrix.sync.aligned.m8n8.x4.trans.shared.b16 {%0,%1,%2,%3}, [%4];"
                 : "=r"(r[0]), "=r"(r[1]), "=r"(r[2]), "=r"(r[3]) : "r"(addr));
}

__device__ __forceinline__ void mma16816(float* d, uint32_t a0, uint32_t a1, uint32_t a2,
                                         uint32_t a3, uint32_t b0, uint32_t b1) {
    asm volatile(
        "mma.sync.aligned.m16n8k16.row.col.f32.f16.f16.f32 "
        "{%0,%1,%2,%3}, {%4,%5,%6,%7}, {%8,%9}, {%0,%1,%2,%3};"
        : "+f"(d[0]), "+f"(d[1]), "+f"(d[2]), "+f"(d[3])
        : "r"(a0), "r"(a1), "r"(a2), "r"(a3), "r"(b0), "r"(b1));
}

__device__ __forceinline__ void cpa16(uint32_t saddr, const void* g) {
    asm volatile("cp.async.cg.shared.global [%0], [%1], 16;" :: "r"(saddr), "l"(g) : "memory");
}

__device__ __forceinline__ uint32_t packhf(float lo, float hi) {
    uint32_t r;
    asm("cvt.rn.f16x2.f32 %0, %1, %2;" : "=r"(r) : "f"(hi), "f"(lo));
    return r;
}
__device__ __forceinline__ float lo_h(uint32_t p) {
    return __half2float(__ushort_as_half((unsigned short)(p & 0xFFFFu)));
}
__device__ __forceinline__ float hi_h(uint32_t p) {
    return __half2float(__ushort_as_half((unsigned short)(p >> 16)));
}

// ---------------------------------------------------------------------------
// Merged conversion: X -> fp16 hi/lo split; weights -> single fp16.
// ---------------------------------------------------------------------------
#define N_X4  1048576
#define N_WQ4 1048576
#define N_WK4 262144
#define N_WV4 262144
#define N_WO4 1048576
#define N_ALL4 (N_X4 + N_WQ4 + N_WK4 + N_WV4 + N_WO4)

__global__ __launch_bounds__(256) void split_all(const float* __restrict__ X,
                                                 const float* __restrict__ Wq,
                                                 const float* __restrict__ Wk,
                                                 const float* __restrict__ Wv,
                                                 const float* __restrict__ Wo)
{
    const int i = blockIdx.x * 256 + threadIdx.x;
    const float* src;
    __half* hi;
    int off;
    bool do_split = false;
    if (i < N_X4)                       { src = X;  hi = g_Xh; off = i; do_split = true; }
    else if (i < N_X4 + N_WQ4)          { src = Wq; hi = g_Wq; off = i - N_X4; }
    else if (i < N_X4 + N_WQ4 + N_WK4)  { src = Wk; hi = g_Wk; off = i - N_X4 - N_WQ4; }
    else if (i < N_X4 + N_WQ4 + N_WK4 + N_WV4)
                                        { src = Wv; hi = g_Wv; off = i - N_X4 - N_WQ4 - N_WK4; }
    else                                { src = Wo; hi = g_Wo; off = i - N_X4 - N_WQ4 - N_WK4 - N_WV4; }

    float4 v = ((const float4*)src)[off];
    float f[4] = {v.x, v.y, v.z, v.w};
    __half h[4];
#pragma unroll
    for (int k = 0; k < 4; ++k) h[k] = __float2half_rn(f[k]);
    *(uint64_t*)(hi + 4 * off) = *(uint64_t*)h;
    if (do_split) {
        __half l[4];
#pragma unroll
        for (int k = 0; k < 4; ++k) l[k] = __float2half_rn(f[k] - __half2float(h[k]));
        *(uint64_t*)(g_Xl + 4 * off) = *(uint64_t*)l;
    }
}

// ---------------------------------------------------------------------------
// 128x128 fp16 HMMA GEMM, K-tile 64, 2-stage cp.async (r11 proven).
// MODE 0 (fused QKV): A = Xh+Xl (2-term), B single.  3 tiles/stage, 110.6 KB.
// MODE 1 (O proj):    A = Ch (1-term),   B = Wo.     2 tiles/stage,  73.7 KB.
// ---------------------------------------------------------------------------
#define T64_H 9216
#define T64_B (T64_H * 2)

template <int MODE>
__global__ __launch_bounds__(256) void hgemm6_k(const float* __restrict__ bq,
                                                const float* __restrict__ bk,
                                                const float* __restrict__ bv,
                                                float* __restrict__ outp)
{
    constexpr int NTERMS = (MODE == 0) ? 2 : 1;
    constexpr int NTILES = NTERMS + 1;
    constexpr uint32_t STAGE_B = NTILES * T64_B;
    constexpr uint32_t BOFF = NTERMS * T64_B;

    extern __shared__ __half sm[];
    const int t = threadIdx.x, w = t >> 5, lane = t & 31;
    const int bm = blockIdx.y * 128;
    const int bn = blockIdx.x * 128;
    const int wm = (w & 3) * 32, wn = (w >> 2) * 64;

    const __half* srcs[NTILES];
    const float* bias = nullptr;
    int outsel, bcol0;
    if (MODE == 0) {
        const __half* B;
        if (bn < 2048)      { B = g_Wq; bias = bq; outsel = 0; bcol0 = bn; }
        else if (bn < 2560) { B = g_Wk; bias = bk; outsel = 1; bcol0 = bn - 2048; }
        else                { B = g_Wv; bias = bv; outsel = 2; bcol0 = bn - 2560; }
        srcs[0] = g_Xh + (size_t)bm * HID;
        srcs[1] = g_Xl + (size_t)bm * HID;
        srcs[NTERMS] = B + (size_t)bcol0 * HID;
    } else {
        outsel = 3; bcol0 = bn;
        srcs[0] = g_Ch + (size_t)bm * HID;
        srcs[NTERMS] = g_Wo + (size_t)bcol0 * HID;
    }

    const uint32_t sb = s2u(sm);
    const uint32_t a_r = lane & 15, a_c8 = (lane >> 4) << 3;
    const uint32_t b_r = ((lane >> 4) << 3) + (lane & 7), b_c8 = ((lane >> 3) & 1) << 3;

    float acc[2][8][4];
#pragma unroll
    for (int mi = 0; mi < 2; ++mi)
#pragma unroll
        for (int ni = 0; ni < 8; ++ni)
#pragma unroll
            for (int r = 0; r < 4; ++r) acc[mi][ni][r] = 0.0f;

#define ISSUE(ktv, stg)                                                              \
    {                                                                                \
        const int _kt = (ktv);                                                       \
        const uint32_t _sb0 = sb + (uint32_t)(stg) * STAGE_B;                        \
        _Pragma("unroll")                                                            \
        for (int i = 0; i < 4 * NTILES; ++i) {                                       \
            const int idx = i * 256 + t;                                             \
            const int tile = idx >> 10;                                              \
            const int rem = idx & 1023;                                              \
            const int row = rem >> 3, ch = rem & 7;                                  \
            cpa16(_sb0 + (uint32_t)(tile * T64_H + row * 72 + ch * 8) * 2,           \
                  srcs[tile] + (size_t)row * HID + _kt + ch * 8);                    \
        }                                                                            \
        asm volatile("cp.async.commit_group;" ::: "memory");                         \
    }

    ISSUE(0, 0);

    for (int it = 0; it < HID / 64; ++it) {
        const int cur = it & 1;
        if (it < HID / 64 - 1) {
            ISSUE((it + 1) * 64, cur ^ 1);
            asm volatile("cp.async.wait_group 1;" ::: "memory");
        } else {
            asm volatile("cp.async.wait_group 0;" ::: "memory");
        }
        __syncthreads();

        const uint32_t st = sb + (uint32_t)cur * STAGE_B;
#pragma unroll
        for (int ks = 0; ks < 4; ++ks) {
            const uint32_t k0 = ks * 16;
            uint32_t bf[4][4];
#pragma unroll
            for (int pi = 0; pi < 4; ++pi) {
                uint32_t off = ((wn + pi * 16 + b_r) * 72 + k0 + b_c8) * 2;
                ldsm4(bf[pi], st + BOFF + off);
            }
#pragma unroll
            for (int mi = 0; mi < 2; ++mi) {
                uint32_t ah[4], al[4];
                uint32_t off = ((wm + mi * 16 + a_r) * 72 + k0 + a_c8) * 2;
                ldsm4(ah, st + 0 * T64_B + off);
                if (NTERMS == 2) ldsm4(al, st + 1 * T64_B + off);
#pragma unroll
                for (int pi = 0; pi < 4; ++pi) {
#pragma unroll
                    for (int half = 0; half < 2; ++half) {
                        const int ni = pi * 2 + half;
                        const uint32_t B0 = bf[pi][half * 2], B1 = bf[pi][half * 2 + 1];
                        mma16816(acc[mi][ni], ah[0], ah[1], ah[2], ah[3], B0, B1);
                        if (NTERMS == 2)
                            mma16816(acc[mi][ni], al[0], al[1], al[2], al[3], B0, B1);
                    }
                }
            }
        }
        __syncthreads();
    }
#undef ISSUE

#pragma unroll
    for (int mi = 0; mi < 2; ++mi) {
#pragma unroll
        for (int ni = 0; ni < 8; ++ni) {
            const int lcol = wn + ni * 8 + 2 * (lane & 3);
            const int col = bcol0 + lcol;
            float b0 = 0.f, b1 = 0.f;
            if (MODE == 0) { b0 = bias[col]; b1 = bias[col + 1]; }
#pragma unroll
            for (int rr = 0; rr < 2; ++rr) {
                const int row = bm + wm + mi * 16 + (lane >> 2) + rr * 8;
                float vx = acc[mi][ni][rr * 2 + 0] + b0;
                float vy = acc[mi][ni][rr * 2 + 1] + b1;
                if (outsel == 0 || outsel == 1) {
                    const int head = col >> 6, d = col & 63;
                    float* dst = (outsel == 0) ? g_q : g_k;
                    float2 v2 = {vx, vy};
                    *(float2*)(dst + ((size_t)head * S_LEN + row) * HD + d) = v2;
                } else if (outsel == 2) {
                    const int head = col >> 6, d = col & 63;
                    *(uint32_t*)(g_vh + ((size_t)head * S_LEN + row) * HD + d) = packhf(vx, vy);
                } else {
                    float2 v2 = {vx, vy};
                    *(float2*)(outp + (size_t)row * HID + col) = v2;
                }
            }
        }
    }
}

#define GEMM_SMEM0 (2 * 3 * T64_B)
#define GEMM_SMEM1 (2 * 2 * T64_B)

// ---------------------------------------------------------------------------
// RoPE: Q -> fp16 hi/lo split; K -> single fp16.
// ---------------------------------------------------------------------------
#define ROPE_Q_N (NH * S_LEN * 16)
#define ROPE_K_N (NKV * S_LEN * 16)

__global__ __launch_bounds__(256) void rope_all()
{
    int idx = blockIdx.x * 256 + threadIdx.x;
    const bool isQ = (idx < ROPE_Q_N);
    if (!isQ) idx -= ROPE_Q_N;

    const int j2 = (idx & 15) * 2;
    const int s = (idx >> 4) & (S_LEN - 1);
    const int h = idx >> 15;
    const size_t base = ((size_t)h * S_LEN + s) * HD;

    const float* src = (isQ ? g_q : g_k) + base;
    float y1[2], y2[2];
#pragma unroll
    for (int e = 0; e < 2; ++e) {
        const int j = j2 + e;
        const float inv_freq = powf(10000.0f, -((float)(2 * j)) / 64.0f);
        float sn, cs;
        sincosf((float)s * inv_freq, &sn, &cs);
        const float x1 = src[j], x2 = src[j + 32];
        y1[e] = x1 * cs - x2 * sn;
        y2[e] = x2 * cs + x1 * sn;
    }
    const uint32_t p1 = packhf(y1[0], y1[1]);
    const uint32_t p2 = packhf(y2[0], y2[1]);
    if (isQ) {
        *(uint32_t*)(g_qh + base + j2) = p1;
        *(uint32_t*)(g_qh + base + j2 + 32) = p2;
        *(uint32_t*)(g_ql + base + j2) = packhf(y1[0] - lo_h(p1), y1[1] - hi_h(p1));
        *(uint32_t*)(g_ql + base + j2 + 32) = packhf(y2[0] - lo_h(p2), y2[1] - hi_h(p2));
    } else {
        *(uint32_t*)(g_kh + base + j2) = p1;
        *(uint32_t*)(g_kh + base + j2 + 32) = p2;
    }
}

// ---------------------------------------------------------------------------
// HMMA flash attention: 2-term QK^T, SINGLE-term PV (P truncated to fp16).
// Split K/V cp.async pipeline. smem 46080 B, 3 CTAs/SM.
// ---------------------------------------------------------------------------
#define TILE_B 9216
#define AT_QH 0
#define AT_QL 9216
#define AT_K0 18432
#define AT_K1 27648
#define AT_V  36864
#define ATTN_SMEM 46080

__global__ __launch_bounds__(128, 3) void attn_k()
{
    extern __shared__ __half smb[];
    const uint32_t sb = s2u(smb);
    const int h = blockIdx.y;
    const int zz = blockIdx.x;
    const int qb = (zz & 1) ? (31 - (zz >> 1)) : (zz >> 1);
    const int kvh = h >> 2;

    const int t = threadIdx.x, w = t >> 5, lane = t & 31;
    const size_t kvbase = (size_t)kvh * S_LEN * HD;

#define CPT(dstoff, src)                                                            \
    {                                                                               \
        _Pragma("unroll")                                                           \
        for (int ii = 0; ii < 4; ++ii) {                                            \
            const int rem = ii * 128 + t;                                           \
            const int row = rem >> 3, ch = rem & 7;                                 \
            cpa16(sb + (dstoff) + (row * 72 + ch * 8) * 2,                          \
                  (src) + row * 64 + ch * 8);                                       \
        }                                                                           \
        asm volatile("cp.async.commit_group;" ::: "memory");                        \
    }

    CPT(AT_K0, g_kh + kvbase);

    {
        const __half* qh = g_qh + ((size_t)h * S_LEN + (size_t)qb * 64) * HD;
        const __half* ql = g_ql + ((size_t)h * S_LEN + (size_t)qb * 64) * HD;
#pragma unroll
        for (int ii = 0; ii < 4; ++ii) {
            const int i = ii * 128 + t;
            const int row = i >> 3, ch = i & 7;
            *(uint4*)((char*)smb + AT_QH + (row * 72 + ch * 8) * 2) =
                *(const uint4*)(qh + row * 64 + ch * 8);
            *(uint4*)((char*)smb + AT_QL + (row * 72 + ch * 8) * 2) =
                *(const uint4*)(ql + row * 64 + ch * 8);
        }
    }
    __syncthreads();

    const uint32_t a_r = lane & 15, a_c8 = (lane >> 4) << 3;
    const uint32_t b_r = ((lane >> 4) << 3) + (lane & 7), b_c8 = ((lane >> 3) & 1) << 3;
    uint32_t qfh[4][4], qfl[4][4];
#pragma unroll
    for (int ks = 0; ks < 4; ++ks) {
        uint32_t off = ((w * 16 + a_r) * 72 + ks * 16 + a_c8) * 2;
        ldsm4(qfh[ks], sb + AT_QH + off);
        ldsm4(qfl[ks], sb + AT_QL + off);
    }

    float oacc[8][4];
#pragma unroll
    for (int nt = 0; nt < 8; ++nt)
#pragma unroll
        for (int e = 0; e < 4; ++e) oacc[nt][e] = 0.0f;
    float m_i[2] = {-1e30f, -1e30f}, l_i[2] = {0.0f, 0.0f};

    const int grow0 = qb * 64 + w * 16 + (lane >> 2);

    for (int kb = 0; kb <= qb; ++kb) {
        const uint32_t KHB = (kb & 1) ? AT_K1 : AT_K0;
        __syncthreads();
        CPT(AT_V, g_vh + kvbase + (size_t)kb * 64 * HD);
        asm volatile("cp.async.wait_group 1;" ::: "memory");
        __syncthreads();

        // ---- S = Q K^T (2-term) ----
        float sacc[8][4];
#pragma unroll
        for (int nt = 0; nt < 8; ++nt)
#pragma unroll
            for (int e = 0; e < 4; ++e) sacc[nt][e] = 0.0f;

#pragma unroll
        for (int ks = 0; ks < 4; ++ks) {
#pragma unroll
            for (int np = 0; np < 4; ++np) {
                uint32_t BH[4];
                uint32_t off = ((np * 16 + b_r) * 72 + ks * 16 + b_c8) * 2;
                ldsm4(BH, sb + KHB + off);
#pragma unroll
                for (int half = 0; half < 2; ++half) {
                    const int nt = np * 2 + half;
                    mma16816(sacc[nt], qfh[ks][0], qfh[ks][1], qfh[ks][2], qfh[ks][3],
                             BH[half * 2], BH[half * 2 + 1]);
                    mma16816(sacc[nt], qfl[ks][0], qfl[ks][1], qfl[ks][2], qfl[ks][3],
                             BH[half * 2], BH[half * 2 + 1]);
                }
            }
        }

        if (kb < qb) {
            const uint32_t nstage = (kb & 1) ? AT_K0 : AT_K1;
            CPT(nstage, g_kh + kvbase + (size_t)(kb + 1) * 64 * HD);
        }

        // ---- online softmax ----
        const bool diag = (kb == qb);
        float mt[2] = {-1e30f, -1e30f};
#pragma unroll
        for (int nt = 0; nt < 8; ++nt) {
#pragma unroll
            for (int e = 0; e < 4; ++e) {
                float v = sacc[nt][e] * 0.125f;
                v = fminf(fmaxf(v, -50.0f), 50.0f);
                if (diag) {
                    const int col = kb * 64 + nt * 8 + 2 * (lane & 3) + (e & 1);
                    const int row = grow0 + (e >> 1) * 8;
                    if (col > row) v = -1e30f;
                }
                sacc[nt][e] = v;
                mt[e >> 1] = fmaxf(mt[e >> 1], v);
            }
        }
#pragma unroll
        for (int o = 1; o < 4; o <<= 1) {
            mt[0] = fmaxf(mt[0], __shfl_xor_sync(0xffffffffu, mt[0], o));
            mt[1] = fmaxf(mt[1], __shfl_xor_sync(0xffffffffu, mt[1], o));
        }
        float corr[2], rs[2] = {0.0f, 0.0f};
#pragma unroll
        for (int rr = 0; rr < 2; ++rr) {
            const float mn = fmaxf(m_i[rr], mt[rr]);
            corr[rr] = __expf(m_i[rr] - mn);
            m_i[rr] = mn;
        }
#pragma unroll
        for (int nt = 0; nt < 8; ++nt)
#pragma unroll
            for (int e = 0; e < 4; ++e) {
                const float p = __expf(sacc[nt][e] - m_i[e >> 1]);
                sacc[nt][e] = p;
                rs[e >> 1] += p;
            }
#pragma unroll
        for (int o = 1; o < 4; o <<= 1) {
            rs[0] += __shfl_xor_sync(0xffffffffu, rs[0], o);
            rs[1] += __shfl_xor_sync(0xffffffffu, rs[1], o);
        }
#pragma unroll
        for (int rr = 0; rr < 2; ++rr) l_i[rr] = l_i[rr] * corr[rr] + rs[rr];
#pragma unroll
        for (int nt = 0; nt < 8; ++nt)
#pragma unroll
            for (int e = 0; e < 4; ++e) oacc[nt][e] *= corr[e >> 1];

        // ---- wait V, then PV (single-term fp16 P) ----
        if (kb < qb) asm volatile("cp.async.wait_group 1;" ::: "memory");
        else         asm volatile("cp.async.wait_group 0;" ::: "memory");
        __syncthreads();

#pragma unroll
        for (int ks = 0; ks < 4; ++ks) {
            const int L = 2 * ks, R = 2 * ks + 1;
            uint32_t ph[4];
            ph[0] = packhf(sacc[L][0], sacc[L][1]);
            ph[1] = packhf(sacc[L][2], sacc[L][3]);
            ph[2] = packhf(sacc[R][0], sacc[R][1]);
            ph[3] = packhf(sacc[R][2], sacc[R][3]);
#pragma unroll
            for (int dp = 0; dp < 4; ++dp) {
                uint32_t VH4[4];
                uint32_t voff = ((ks * 16 + (lane & 7) + ((lane >> 3) & 1) * 8) * 72
                                 + dp * 16 + ((lane >> 4) << 3)) * 2;
                ldsm4t(VH4, sb + AT_V + voff);
#pragma unroll
                for (int half = 0; half < 2; ++half) {
                    const int nt = dp * 2 + half;
                    mma16816(oacc[nt], ph[0], ph[1], ph[2], ph[3],
                             VH4[half * 2], VH4[half * 2 + 1]);
                }
            }
        }
    }
#undef CPT

    // ---- epilogue: normalize, single-fp16 store ----
    const float inv0 = 1.0f / l_i[0], inv1 = 1.0f / l_i[1];
#pragma unroll
    for (int nt = 0; nt < 8; ++nt) {
#pragma unroll
        for (int rr = 0; rr < 2; ++rr) {
            const float inv = rr ? inv1 : inv0;
            const float v0 = oacc[nt][rr * 2 + 0] * inv;
            const float v1 = oacc[nt][rr * 2 + 1] * inv;
            const int srow = qb * 64 + w * 16 + (lane >> 2) + rr * 8;
            const int col = h * 64 + nt * 8 + 2 * (lane & 3);
            *(uint32_t*)(g_Ch + (size_t)srow * HID + col) = packhf(v0, v1);
        }
    }
}

// ---------------------------------------------------------------------------
// Launcher
// ---------------------------------------------------------------------------
extern "C" void kernel_launch(void* const* d_in, const int* in_sizes, int n_in,
                              void* d_out, int out_size)
{
    const float* X  = (const float*)d_in[0];
    const float* Wq = (const float*)d_in[2];
    const float* bq = (const float*)d_in[3];
    const float* Wk = (const float*)d_in[4];
    const float* bk = (const float*)d_in[5];
    const float* Wv = (const float*)d_in[6];
    const float* bv = (const float*)d_in[7];
    const float* Wo = (const float*)d_in[8];
    float* out = (float*)d_out;

    split_all<<<N_ALL4 / 256, 256>>>(X, Wq, Wk, Wv, Wo);

    cudaFuncSetAttribute(hgemm6_k<0>, cudaFuncAttributeMaxDynamicSharedMemorySize, GEMM_SMEM0);
    cudaFuncSetAttribute(hgemm6_k<1>, cudaFuncAttributeMaxDynamicSharedMemorySize, GEMM_SMEM1);

    hgemm6_k<0><<<dim3(24, S_LEN / 128), 256, GEMM_SMEM0>>>(bq, bk, bv, nullptr);

    rope_all<<<(ROPE_Q_N + ROPE_K_N) / 256, 256>>>();

    cudaFuncSetAttribute(attn_k, cudaFuncAttributeMaxDynamicSharedMemorySize, ATTN_SMEM);
    attn_k<<<dim3(32, NH), 128, ATTN_SMEM>>>();

    hgemm6_k<1><<<dim3(16, S_LEN / 128), 256, GEMM_SMEM1>>>(nullptr, nullptr, nullptr, out);
}